// round 9
// baseline (speedup 1.0000x reference)
#include <cuda_runtime.h>
#include <cstdint>

#define S_LEN 4096
#define CCH   512
#define NH    8
#define DH    64
#define BATCH 2

// Scratch: tf32 BIT PATTERNS. g_q/g_k: [bh][s][d]; g_v TRANSPOSED: [bh][d][s].
__device__ float g_q[(size_t)BATCH * NH * S_LEN * DH];   // pre-scaled by 1/8
__device__ float g_k[(size_t)BATCH * NH * S_LEN * DH];
__device__ float g_v[(size_t)BATCH * NH * S_LEN * DH];
__device__ float g_attnout[(size_t)BATCH * S_LEN * CCH]; // fp32

__device__ __forceinline__ uint32_t f2tf(float x) {
    uint32_t u; asm("cvt.rna.tf32.f32 %0, %1;" : "=r"(u) : "f"(x)); return u;
}
__device__ __forceinline__ float f2tff(float x) { return __uint_as_float(f2tf(x)); }

__device__ __forceinline__ void mma8(float d[4], const uint32_t a[4], const uint32_t b[2]) {
    asm volatile(
        "mma.sync.aligned.m16n8k8.row.col.f32.tf32.tf32.f32 "
        "{%0,%1,%2,%3}, {%4,%5,%6,%7}, {%8,%9}, {%0,%1,%2,%3};\n"
        : "+f"(d[0]), "+f"(d[1]), "+f"(d[2]), "+f"(d[3])
        : "r"(a[0]), "r"(a[1]), "r"(a[2]), "r"(a[3]), "r"(b[0]), "r"(b[1]));
}
__device__ __forceinline__ void cp_async16(uint32_t s, const void* g) {
    asm volatile("cp.async.cg.shared.global [%0], [%1], 16;\n" :: "r"(s), "l"(g));
}
__device__ __forceinline__ void cp_commit() { asm volatile("cp.async.commit_group;\n"); }
template<int N> __device__ __forceinline__ void cp_wait() {
    asm volatile("cp.async.wait_group %0;\n" :: "n"(N));
}
__device__ __forceinline__ void ldsm4(uint32_t r[4], uint32_t addr) {
    asm volatile("ldmatrix.sync.aligned.m8n8.x4.shared.b16 {%0,%1,%2,%3}, [%4];"
        : "=r"(r[0]), "=r"(r[1]), "=r"(r[2]), "=r"(r[3]) : "r"(addr));
}

// ============================================================
// Kernel 1: QKV projections (epilogue stores tf32 bits; V transposed)
// ============================================================
__global__ __launch_bounds__(256) void qkv_kernel(
    const float* __restrict__ x, const float* __restrict__ ctx,
    const float* __restrict__ Wq, const float* __restrict__ bq,
    const float* __restrict__ Wk, const float* __restrict__ bk,
    const float* __restrict__ Wv, const float* __restrict__ bv)
{
    const int proj = blockIdx.z >> 1;
    const int b    = blockIdx.z & 1;
    const float* A    = (proj == 0) ? x  : ctx;
    const float* W    = (proj == 0) ? Wq : (proj == 1) ? Wk : Wv;
    const float* bias = (proj == 0) ? bq : (proj == 1) ? bk : bv;
    float* outbuf     = (proj == 0) ? g_q : (proj == 1) ? g_k : g_v;
    const float scale = (proj == 0) ? 0.125f : 1.0f;
    const bool isV    = (proj == 2);

    const int s0 = blockIdx.y * 128;
    const int n0 = blockIdx.x * 128;

    __shared__ float As[16][136];
    __shared__ float Bs[16][136];

    const int tid = threadIdx.x, lane = tid & 31, warp = tid >> 5;
    const int wm = warp >> 2, wn = warp & 3, lr = lane >> 2, lc = lane & 3;

    float acc[4][4][4];
    #pragma unroll
    for (int i = 0; i < 4; i++)
        #pragma unroll
        for (int j = 0; j < 4; j++)
            #pragma unroll
            for (int k = 0; k < 4; k++) acc[i][j][k] = 0.f;

    const float* Ab = A + (size_t)b * CCH * S_LEN;

    for (int kb = 0; kb < CCH; kb += 16) {
        #pragma unroll
        for (int i = 0; i < 8; i++) {
            int idx = tid + i * 256;
            int m = idx & 127, k = idx >> 7;
            As[k][m] = f2tff(Ab[(size_t)(kb + k) * S_LEN + s0 + m]);
        }
        #pragma unroll
        for (int i = 0; i < 2; i++) {
            int idx = tid + i * 256;
            int k4 = idx & 3, n = idx >> 2;
            float4 v = *(const float4*)(W + (size_t)(n0 + n) * CCH + kb + k4 * 4);
            Bs[k4 * 4 + 0][n] = f2tff(v.x);
            Bs[k4 * 4 + 1][n] = f2tff(v.y);
            Bs[k4 * 4 + 2][n] = f2tff(v.z);
            Bs[k4 * 4 + 3][n] = f2tff(v.w);
        }
        __syncthreads();

        #pragma unroll
        for (int kk = 0; kk < 16; kk += 8) {
            uint32_t af[4][4];
            #pragma unroll
            for (int mt = 0; mt < 4; mt++) {
                int r = wm * 64 + mt * 16 + lr;
                af[mt][0] = __float_as_uint(As[kk + lc][r]);
                af[mt][1] = __float_as_uint(As[kk + lc][r + 8]);
                af[mt][2] = __float_as_uint(As[kk + 4 + lc][r]);
                af[mt][3] = __float_as_uint(As[kk + 4 + lc][r + 8]);
            }
            uint32_t bf[4][2];
            #pragma unroll
            for (int nt = 0; nt < 4; nt++) {
                int c = wn * 32 + nt * 8 + lr;
                bf[nt][0] = __float_as_uint(Bs[kk + lc][c]);
                bf[nt][1] = __float_as_uint(Bs[kk + 4 + lc][c]);
            }
            #pragma unroll
            for (int mt = 0; mt < 4; mt++)
                #pragma unroll
                for (int nt = 0; nt < 4; nt++)
                    mma8(acc[mt][nt], af[mt], bf[nt]);
        }
        __syncthreads();
    }

    #pragma unroll
    for (int mt = 0; mt < 4; mt++) {
        #pragma unroll
        for (int nt = 0; nt < 4; nt++) {
            int r = s0 + wm * 64 + mt * 16 + lr;
            int c = n0 + wn * 32 + nt * 8 + 2 * lc;
            float b0 = bias[c], b1 = bias[c + 1];
            int h = c >> 6, d = c & 63;
            float v0 = f2tff((acc[mt][nt][0] + b0) * scale);
            float v1 = f2tff((acc[mt][nt][1] + b1) * scale);
            float v2 = f2tff((acc[mt][nt][2] + b0) * scale);
            float v3 = f2tff((acc[mt][nt][3] + b1) * scale);
            if (!isV) {
                float* obase = outbuf + (((size_t)(b * NH + h)) * S_LEN) * DH + d;
                *(float2*)(obase + (size_t)r * DH)       = make_float2(v0, v1);
                *(float2*)(obase + (size_t)(r + 8) * DH) = make_float2(v2, v3);
            } else {
                // transposed store: g_v[bh][d][s]
                float* vbase = outbuf + ((size_t)(b * NH + h) * DH) * S_LEN;
                vbase[(size_t)(d    ) * S_LEN + r]     = v0;
                vbase[(size_t)(d + 1) * S_LEN + r]     = v1;
                vbase[(size_t)(d    ) * S_LEN + r + 8] = v2;
                vbase[(size_t)(d + 1) * S_LEN + r + 8] = v3;
            }
        }
    }
}

// ============================================================
// Kernel 2: flash attention. LDSM fragment loads everywhere.
// smem floats: Q[128*68] | K0,K1[64*68] | V0,V1[64*68] (V rows = d)
// ============================================================
#define KOFF(p) (128 * 68 + (p) * (64 * 68))
#define VOFF(p) (128 * 68 + 2 * 64 * 68 + (p) * (64 * 68))
#define SMEMA ((128 * 68 + 4 * 64 * 68) * 4)

__device__ __forceinline__ void fill_kv(uint32_t smb, const float* Kg, const float* Vg,
                                        int jt, int p, int tid)
{
    uint32_t kb = smb + KOFF(p) * 4;
    uint32_t vb = smb + VOFF(p) * 4;
    #pragma unroll
    for (int i = 0; i < 4; i++) {
        int idx = tid + i * 256;
        int j = idx >> 4, c4 = idx & 15;
        cp_async16(kb + (uint32_t)(j * 68 + c4 * 4) * 4, Kg + ((size_t)jt * 64 + j) * DH + c4 * 4);
        cp_async16(vb + (uint32_t)(j * 68 + c4 * 4) * 4, Vg + (size_t)j * S_LEN + jt * 64 + c4 * 4);
    }
}

__global__ __launch_bounds__(256, 2) void attn_kernel()
{
    extern __shared__ float sm[];
    const int qt = blockIdx.x, bh = blockIdx.y;
    const int tid = threadIdx.x, lane = tid & 31, warp = tid >> 5;
    const int lr = lane >> 2, lc = lane & 3;
    const int rbase = warp * 16;

    const float* Qg = g_q + (size_t)bh * S_LEN * DH + (size_t)qt * 128 * DH;
    const float* Kg = g_k + (size_t)bh * S_LEN * DH;
    const float* Vg = g_v + (size_t)bh * S_LEN * DH;   // [d][s]

    uint32_t smb = (uint32_t)__cvta_generic_to_shared(sm);

    // LDSM per-thread address components
    const int g8 = lane >> 3, r8 = lane & 7;
    // B-type (K and V): tiles {nt0/klo, nt0/khi, nt1/klo, nt1/khi}
    const uint32_t boff = (uint32_t)((((g8 >> 1) << 3) | r8) * 68 + ((g8 & 1) << 2)) * 4;
    // A-type (Q): tiles {mlo/klo, mhi/klo, mlo/khi, mhi/khi}
    const uint32_t aoff = (uint32_t)((rbase + ((g8 & 1) << 3) + r8) * 68 + ((g8 >> 1) << 2)) * 4;

    // Q fill (group 0)
    #pragma unroll
    for (int i = 0; i < 8; i++) {
        int idx = tid + i * 256;
        int j = idx >> 4, c4 = idx & 15;
        cp_async16(smb + (uint32_t)(j * 68 + c4 * 4) * 4, Qg + (size_t)j * DH + c4 * 4);
    }
    cp_commit();
    fill_kv(smb, Kg, Vg, 0, 0, tid);
    cp_commit();
    cp_wait<1>();
    __syncthreads();

    // Q fragments -> registers via LDSM (8 instructions)
    uint32_t qf[8][4];
    #pragma unroll
    for (int kt = 0; kt < 8; kt++)
        ldsm4(qf[kt], smb + aoff + (uint32_t)(kt * 8) * 4);

    float o[8][4];
    #pragma unroll
    for (int i = 0; i < 8; i++)
        #pragma unroll
        for (int j = 0; j < 4; j++) o[i][j] = 0.f;
    float m0 = -1e30f, m1 = -1e30f, l0 = 0.f, l1 = 0.f;

    const int srcA = (lane & 28) | (lc >> 1);
    const int srcB = srcA + 2;
    const bool odd = lc & 1;

    for (int jt = 0; jt < 64; jt++) {
        const int p = jt & 1;
        __syncthreads();
        if (jt < 63) { fill_kv(smb, Kg, Vg, jt + 1, p ^ 1, tid); cp_commit(); cp_wait<1>(); }
        else         { cp_wait<0>(); }
        __syncthreads();

        const uint32_t Kb = smb + KOFF(p) * 4 + boff;
        const uint32_t Vb = smb + VOFF(p) * 4 + boff;

        // S = Q K^T via LDSM B fragments
        float s[8][4];
        #pragma unroll
        for (int i = 0; i < 8; i++)
            #pragma unroll
            for (int j2 = 0; j2 < 4; j2++) s[i][j2] = 0.f;

        #pragma unroll
        for (int kt = 0; kt < 8; kt++) {
            #pragma unroll
            for (int p2 = 0; p2 < 4; p2++) {
                uint32_t bb[4];
                ldsm4(bb, Kb + (uint32_t)(p2 * 16 * 68 + kt * 8) * 4);
                mma8(s[2 * p2],     qf[kt], bb);
                mma8(s[2 * p2 + 1], qf[kt], bb + 2);
            }
        }

        // Online softmax (identical statement order)
        float mx0 = s[0][0], mx1 = s[0][2];
        #pragma unroll
        for (int nt = 0; nt < 8; nt++) {
            mx0 = fmaxf(mx0, fmaxf(s[nt][0], s[nt][1]));
            mx1 = fmaxf(mx1, fmaxf(s[nt][2], s[nt][3]));
        }
        mx0 = fmaxf(mx0, __shfl_xor_sync(0xffffffffu, mx0, 1));
        mx0 = fmaxf(mx0, __shfl_xor_sync(0xffffffffu, mx0, 2));
        mx1 = fmaxf(mx1, __shfl_xor_sync(0xffffffffu, mx1, 1));
        mx1 = fmaxf(mx1, __shfl_xor_sync(0xffffffffu, mx1, 2));
        float mn0 = fmaxf(m0, mx0), mn1 = fmaxf(m1, mx1);
        float f0 = __expf(m0 - mn0), f1 = __expf(m1 - mn1);
        float sum0 = 0.f, sum1 = 0.f;
        #pragma unroll
        for (int nt = 0; nt < 8; nt++) {
            s[nt][0] = __expf(s[nt][0] - mn0); sum0 += s[nt][0];
            s[nt][1] = __expf(s[nt][1] - mn0); sum0 += s[nt][1];
            s[nt][2] = __expf(s[nt][2] - mn1); sum1 += s[nt][2];
            s[nt][3] = __expf(s[nt][3] - mn1); sum1 += s[nt][3];
        }
        sum0 += __shfl_xor_sync(0xffffffffu, sum0, 1);
        sum0 += __shfl_xor_sync(0xffffffffu, sum0, 2);
        sum1 += __shfl_xor_sync(0xffffffffu, sum1, 1);
        sum1 += __shfl_xor_sync(0xffffffffu, sum1, 2);
        l0 = l0 * f0 + sum0;
        l1 = l1 * f1 + sum1;
        m0 = mn0; m1 = mn1;
        #pragma unroll
        for (int dt = 0; dt < 8; dt++) {
            o[dt][0] *= f0; o[dt][1] *= f0; o[dt][2] *= f1; o[dt][3] *= f1;
        }

        // P -> tf32 bits (after fp32 sums)
        #pragma unroll
        for (int nt = 0; nt < 8; nt++)
            #pragma unroll
            for (int e = 0; e < 4; e++) s[nt][e] = f2tff(s[nt][e]);

        // O += P V : A via shuffles, B via LDSM from transposed V
        #pragma unroll
        for (int kt = 0; kt < 8; kt++) {
            float u0 = __shfl_sync(0xffffffffu, s[kt][0], srcA);
            float u1 = __shfl_sync(0xffffffffu, s[kt][1], srcA);
            float u2 = __shfl_sync(0xffffffffu, s[kt][2], srcA);
            float u3 = __shfl_sync(0xffffffffu, s[kt][3], srcA);
            float w0 = __shfl_sync(0xffffffffu, s[kt][0], srcB);
            float w1 = __shfl_sync(0xffffffffu, s[kt][1], srcB);
            float w2 = __shfl_sync(0xffffffffu, s[kt][2], srcB);
            float w3 = __shfl_sync(0xffffffffu, s[kt][3], srcB);
            uint32_t a[4];
            a[0] = __float_as_uint(odd ? u1 : u0);
            a[1] = __float_as_uint(odd ? u3 : u2);
            a[2] = __float_as_uint(odd ? w1 : w0);
            a[3] = __float_as_uint(odd ? w3 : w2);
            #pragma unroll
            for (int pd = 0; pd < 4; pd++) {
                uint32_t bb[4];
                ldsm4(bb, Vb + (uint32_t)(pd * 16 * 68 + kt * 8) * 4);
                mma8(o[2 * pd],     a, bb);
                mma8(o[2 * pd + 1], a, bb + 2);
            }
        }
    }

    float inv0 = 1.f / l0, inv1 = 1.f / l1;
    const int b = bh >> 3, h = bh & 7;
    const int srow0 = qt * 128 + rbase + lr;
    float* obase = g_attnout + (size_t)b * S_LEN * CCH + (size_t)h * DH;
    #pragma unroll
    for (int dt = 0; dt < 8; dt++) {
        int d = dt * 8 + 2 * lc;
        *(float2*)(obase + (size_t)srow0 * CCH + d) =
            make_float2(o[dt][0] * inv0, o[dt][1] * inv0);
        *(float2*)(obase + (size_t)(srow0 + 8) * CCH + d) =
            make_float2(o[dt][2] * inv1, o[dt][3] * inv1);
    }
}

// ============================================================
// Kernel 3: output projection + transpose store to [b][c][s]
// ============================================================
__global__ __launch_bounds__(256) void oproj_kernel(
    const float* __restrict__ Wo, const float* __restrict__ bo, float* __restrict__ out)
{
    const int m0 = blockIdx.y * 128;
    const int n0 = blockIdx.x * 128;

    __shared__ float As[16][136];
    __shared__ float Bs[16][136];

    const int tid = threadIdx.x, lane = tid & 31, warp = tid >> 5;
    const int wm = warp >> 2, wn = warp & 3, lr = lane >> 2, lc = lane & 3;

    float acc[4][4][4];
    #pragma unroll
    for (int i = 0; i < 4; i++)
        #pragma unroll
        for (int j = 0; j < 4; j++)
            #pragma unroll
            for (int k = 0; k < 4; k++) acc[i][j][k] = 0.f;

    for (int kb = 0; kb < CCH; kb += 16) {
        #pragma unroll
        for (int i = 0; i < 2; i++) {
            int idx = tid + i * 256;
            int k4 = idx & 3, m = idx >> 2;
            float4 v = *(const float4*)(g_attnout + (size_t)(m0 + m) * CCH + kb + k4 * 4);
            As[k4 * 4 + 0][m] = f2tff(v.x);
            As[k4 * 4 + 1][m] = f2tff(v.y);
            As[k4 * 4 + 2][m] = f2tff(v.z);
            As[k4 * 4 + 3][m] = f2tff(v.w);
        }
        #pragma unroll
        for (int i = 0; i < 2; i++) {
            int idx = tid + i * 256;
            int k4 = idx & 3, n = idx >> 2;
            float4 v = *(const float4*)(Wo + (size_t)(n0 + n) * CCH + kb + k4 * 4);
            Bs[k4 * 4 + 0][n] = f2tff(v.x);
            Bs[k4 * 4 + 1][n] = f2tff(v.y);
            Bs[k4 * 4 + 2][n] = f2tff(v.z);
            Bs[k4 * 4 + 3][n] = f2tff(v.w);
        }
        __syncthreads();

        #pragma unroll
        for (int kk = 0; kk < 16; kk += 8) {
            uint32_t af[4][4];
            #pragma unroll
            for (int mt = 0; mt < 4; mt++) {
                int r = wm * 64 + mt * 16 + lr;
                af[mt][0] = __float_as_uint(As[kk + lc][r]);
                af[mt][1] = __float_as_uint(As[kk + lc][r + 8]);
                af[mt][2] = __float_as_uint(As[kk + 4 + lc][r]);
                af[mt][3] = __float_as_uint(As[kk + 4 + lc][r + 8]);
            }
            uint32_t bf[4][2];
            #pragma unroll
            for (int nt = 0; nt < 4; nt++) {
                int c = wn * 32 + nt * 8 + lr;
                bf[nt][0] = __float_as_uint(Bs[kk + lc][c]);
                bf[nt][1] = __float_as_uint(Bs[kk + 4 + lc][c]);
            }
            #pragma unroll
            for (int mt = 0; mt < 4; mt++)
                #pragma unroll
                for (int nt = 0; nt < 4; nt++)
                    mma8(acc[mt][nt], af[mt], bf[nt]);
        }
        __syncthreads();
    }

    #pragma unroll
    for (int mt = 0; mt < 4; mt++) {
        #pragma unroll
        for (int nt = 0; nt < 4; nt++) {
            int r = m0 + wm * 64 + mt * 16 + lr;
            int c = n0 + wn * 32 + nt * 8 + 2 * lc;
            int bb = r >> 12, ss = r & 4095;
            float bias0 = bo[c], bias1 = bo[c + 1];
            float* pc  = out + ((size_t)bb * CCH + c) * S_LEN;
            float* pc1 = pc + S_LEN;
            pc[ss]      = acc[mt][nt][0] + bias0;
            pc1[ss]     = acc[mt][nt][1] + bias1;
            pc[ss + 8]  = acc[mt][nt][2] + bias0;
            pc1[ss + 8] = acc[mt][nt][3] + bias1;
        }
    }
}

// ============================================================
extern "C" void kernel_launch(void* const* d_in, const int* in_sizes, int n_in,
                              void* d_out, int out_size)
{
    const float* x   = (const float*)d_in[0];
    const float* ctx = (const float*)d_in[1];
    const float* Wq  = (const float*)d_in[2];
    const float* bq  = (const float*)d_in[3];
    const float* Wk  = (const float*)d_in[4];
    const float* bk  = (const float*)d_in[5];
    const float* Wv  = (const float*)d_in[6];
    const float* bv  = (const float*)d_in[7];
    const float* Wo  = (const float*)d_in[8];
    const float* bo  = (const float*)d_in[9];
    float* out = (float*)d_out;

    cudaFuncSetAttribute(attn_kernel, cudaFuncAttributeMaxDynamicSharedMemorySize, SMEMA);

    qkv_kernel<<<dim3(4, 32, 6), 256>>>(x, ctx, Wq, bq, Wk, bk, Wv, bv);
    attn_kernel<<<dim3(32, 16), 256, SMEMA>>>();
    oproj_kernel<<<dim3(4, 64), 256>>>(Wo, bo, out);
}

// round 13
// speedup vs baseline: 1.4688x; 1.4688x over previous
#include <cuda_runtime.h>
#include <cuda_fp16.h>
#include <cstdint>

#define S_LEN 4096
#define CCH   512
#define NH    8
#define DH    64
#define BATCH 2

// Scratch: fp16 Q/K/V. g_q/g_k: [bh][s][d]; g_v TRANSPOSED: [bh][d][s].
__device__ __half g_q[(size_t)BATCH * NH * S_LEN * DH];   // pre-scaled by 1/8
__device__ __half g_k[(size_t)BATCH * NH * S_LEN * DH];
__device__ __half g_v[(size_t)BATCH * NH * S_LEN * DH];
__device__ float  g_attnout[(size_t)BATCH * S_LEN * CCH]; // fp32

__device__ __forceinline__ uint32_t f2tf(float x) {
    uint32_t u; asm("cvt.rna.tf32.f32 %0, %1;" : "=r"(u) : "f"(x)); return u;
}
__device__ __forceinline__ float f2tff(float x) { return __uint_as_float(f2tf(x)); }
// pack two fp32 -> f16x2 (lo, hi) with rn rounding
__device__ __forceinline__ uint32_t packh2(float lo, float hi) {
    uint32_t r; asm("cvt.rn.f16x2.f32 %0, %1, %2;" : "=r"(r) : "f"(hi), "f"(lo)); return r;
}

__device__ __forceinline__ void mma8(float d[4], const uint32_t a[4], const uint32_t b[2]) {
    asm volatile(
        "mma.sync.aligned.m16n8k8.row.col.f32.tf32.tf32.f32 "
        "{%0,%1,%2,%3}, {%4,%5,%6,%7}, {%8,%9}, {%0,%1,%2,%3};\n"
        : "+f"(d[0]), "+f"(d[1]), "+f"(d[2]), "+f"(d[3])
        : "r"(a[0]), "r"(a[1]), "r"(a[2]), "r"(a[3]), "r"(b[0]), "r"(b[1]));
}
__device__ __forceinline__ void mma16(float d[4], const uint32_t a[4], const uint32_t b[2]) {
    asm volatile(
        "mma.sync.aligned.m16n8k16.row.col.f32.f16.f16.f32 "
        "{%0,%1,%2,%3}, {%4,%5,%6,%7}, {%8,%9}, {%0,%1,%2,%3};\n"
        : "+f"(d[0]), "+f"(d[1]), "+f"(d[2]), "+f"(d[3])
        : "r"(a[0]), "r"(a[1]), "r"(a[2]), "r"(a[3]), "r"(b[0]), "r"(b[1]));
}
__device__ __forceinline__ void cp_async16(uint32_t s, const void* g) {
    asm volatile("cp.async.cg.shared.global [%0], [%1], 16;\n" :: "r"(s), "l"(g));
}
__device__ __forceinline__ void cp_commit() { asm volatile("cp.async.commit_group;\n"); }
template<int N> __device__ __forceinline__ void cp_wait() {
    asm volatile("cp.async.wait_group %0;\n" :: "n"(N));
}

// ============================================================
// Kernel 1: QKV projections (tf32 compute; epilogue stores fp16, V transposed)
// ============================================================
__global__ __launch_bounds__(256) void qkv_kernel(
    const float* __restrict__ x, const float* __restrict__ ctx,
    const float* __restrict__ Wq, const float* __restrict__ bq,
    const float* __restrict__ Wk, const float* __restrict__ bk,
    const float* __restrict__ Wv, const float* __restrict__ bv)
{
    const int proj = blockIdx.z >> 1;
    const int b    = blockIdx.z & 1;
    const float* A    = (proj == 0) ? x  : ctx;
    const float* W    = (proj == 0) ? Wq : (proj == 1) ? Wk : Wv;
    const float* bias = (proj == 0) ? bq : (proj == 1) ? bk : bv;
    __half* outbuf    = (proj == 0) ? g_q : (proj == 1) ? g_k : g_v;
    const float scale = (proj == 0) ? 0.125f : 1.0f;
    const bool isV    = (proj == 2);

    const int s0 = blockIdx.y * 128;
    const int n0 = blockIdx.x * 128;

    __shared__ float As[16][136];
    __shared__ float Bs[16][136];

    const int tid = threadIdx.x, lane = tid & 31, warp = tid >> 5;
    const int wm = warp >> 2, wn = warp & 3, lr = lane >> 2, lc = lane & 3;

    float acc[4][4][4];
    #pragma unroll
    for (int i = 0; i < 4; i++)
        #pragma unroll
        for (int j = 0; j < 4; j++)
            #pragma unroll
            for (int k = 0; k < 4; k++) acc[i][j][k] = 0.f;

    const float* Ab = A + (size_t)b * CCH * S_LEN;

    for (int kb = 0; kb < CCH; kb += 16) {
        #pragma unroll
        for (int i = 0; i < 8; i++) {
            int idx = tid + i * 256;
            int m = idx & 127, k = idx >> 7;
            As[k][m] = f2tff(Ab[(size_t)(kb + k) * S_LEN + s0 + m]);
        }
        #pragma unroll
        for (int i = 0; i < 2; i++) {
            int idx = tid + i * 256;
            int k4 = idx & 3, n = idx >> 2;
            float4 v = *(const float4*)(W + (size_t)(n0 + n) * CCH + kb + k4 * 4);
            Bs[k4 * 4 + 0][n] = f2tff(v.x);
            Bs[k4 * 4 + 1][n] = f2tff(v.y);
            Bs[k4 * 4 + 2][n] = f2tff(v.z);
            Bs[k4 * 4 + 3][n] = f2tff(v.w);
        }
        __syncthreads();

        #pragma unroll
        for (int kk = 0; kk < 16; kk += 8) {
            uint32_t af[4][4];
            #pragma unroll
            for (int mt = 0; mt < 4; mt++) {
                int r = wm * 64 + mt * 16 + lr;
                af[mt][0] = __float_as_uint(As[kk + lc][r]);
                af[mt][1] = __float_as_uint(As[kk + lc][r + 8]);
                af[mt][2] = __float_as_uint(As[kk + 4 + lc][r]);
                af[mt][3] = __float_as_uint(As[kk + 4 + lc][r + 8]);
            }
            uint32_t bf[4][2];
            #pragma unroll
            for (int nt = 0; nt < 4; nt++) {
                int c = wn * 32 + nt * 8 + lr;
                bf[nt][0] = __float_as_uint(Bs[kk + lc][c]);
                bf[nt][1] = __float_as_uint(Bs[kk + 4 + lc][c]);
            }
            #pragma unroll
            for (int mt = 0; mt < 4; mt++)
                #pragma unroll
                for (int nt = 0; nt < 4; nt++)
                    mma8(acc[mt][nt], af[mt], bf[nt]);
        }
        __syncthreads();
    }

    #pragma unroll
    for (int mt = 0; mt < 4; mt++) {
        #pragma unroll
        for (int nt = 0; nt < 4; nt++) {
            int r = s0 + wm * 64 + mt * 16 + lr;
            int c = n0 + wn * 32 + nt * 8 + 2 * lc;
            float b0 = bias[c], b1 = bias[c + 1];
            int h = c >> 6, d = c & 63;
            float v0 = (acc[mt][nt][0] + b0) * scale;
            float v1 = (acc[mt][nt][1] + b1) * scale;
            float v2 = (acc[mt][nt][2] + b0) * scale;
            float v3 = (acc[mt][nt][3] + b1) * scale;
            if (!isV) {
                __half* qb = outbuf + ((size_t)(b * NH + h) * S_LEN) * DH + d;
                *(uint32_t*)(qb + (size_t)r * DH)       = packh2(v0, v1);
                *(uint32_t*)(qb + (size_t)(r + 8) * DH) = packh2(v2, v3);
            } else {
                __half* vb = outbuf + ((size_t)(b * NH + h) * DH) * S_LEN;
                vb[(size_t)(d    ) * S_LEN + r]     = __float2half_rn(v0);
                vb[(size_t)(d + 1) * S_LEN + r]     = __float2half_rn(v1);
                vb[(size_t)(d    ) * S_LEN + r + 8] = __float2half_rn(v2);
                vb[(size_t)(d + 1) * S_LEN + r + 8] = __float2half_rn(v3);
            }
        }
    }
}

// ============================================================
// Kernel 2: flash attention, fp16 mma (m16n8k16).
// smem (halves): Q[128][72] | K0,K1[64][72] | V0,V1[64][72]  (stride 72h=144B)
// ============================================================
#define QH   (128 * 72)
#define KOFF(p) (QH + (p) * (64 * 72))
#define VOFF(p) (QH + 2 * 64 * 72 + (p) * (64 * 72))
#define SMEMA ((QH + 4 * 64 * 72) * 2)

__device__ __forceinline__ void fill_kv(uint32_t smb, const __half* Kg, const __half* Vg,
                                        int jt, int p, int tid)
{
    uint32_t kb = smb + KOFF(p) * 2;
    uint32_t vb = smb + VOFF(p) * 2;
    #pragma unroll
    for (int i = 0; i < 2; i++) {
        int idx = tid + i * 256;          // 0..511: 64 rows x 8 chunks(16B)
        int j = idx >> 3, c8 = idx & 7;
        cp_async16(kb + (uint32_t)(j * 72 + c8 * 8) * 2, Kg + ((size_t)jt * 64 + j) * DH + c8 * 8);
        cp_async16(vb + (uint32_t)(j * 72 + c8 * 8) * 2, Vg + (size_t)j * S_LEN + jt * 64 + c8 * 8);
    }
}

__global__ __launch_bounds__(256) void attn_kernel()
{
    extern __shared__ __half smh[];
    const int qt = blockIdx.x, bh = blockIdx.y;
    const int tid = threadIdx.x, lane = tid & 31, warp = tid >> 5;
    const int lr = lane >> 2, lc = lane & 3;
    const int rbase = warp * 16;

    const __half* Qg = g_q + (size_t)bh * S_LEN * DH + (size_t)qt * 128 * DH;
    const __half* Kg = g_k + (size_t)bh * S_LEN * DH;
    const __half* Vg = g_v + (size_t)bh * S_LEN * DH;   // [d][s]

    uint32_t smb = (uint32_t)__cvta_generic_to_shared(smh);

    // Q fill (group 0): 128 rows x 8 chunks
    #pragma unroll
    for (int i = 0; i < 4; i++) {
        int idx = tid + i * 256;
        int j = idx >> 3, c8 = idx & 7;
        cp_async16(smb + (uint32_t)(j * 72 + c8 * 8) * 2, Qg + (size_t)j * DH + c8 * 8);
    }
    cp_commit();
    fill_kv(smb, Kg, Vg, 0, 0, tid);
    cp_commit();
    cp_wait<1>();
    __syncthreads();

    // Q fragments (m16n8k16 A) -> registers
    uint32_t qf[4][4];
    #pragma unroll
    for (int kt = 0; kt < 4; kt++) {
        int r = rbase + lr;
        qf[kt][0] = *(const uint32_t*)&smh[(size_t)r * 72 + kt * 16 + 2 * lc];
        qf[kt][1] = *(const uint32_t*)&smh[(size_t)(r + 8) * 72 + kt * 16 + 2 * lc];
        qf[kt][2] = *(const uint32_t*)&smh[(size_t)r * 72 + kt * 16 + 2 * lc + 8];
        qf[kt][3] = *(const uint32_t*)&smh[(size_t)(r + 8) * 72 + kt * 16 + 2 * lc + 8];
    }

    float o[8][4];
    #pragma unroll
    for (int i = 0; i < 8; i++)
        #pragma unroll
        for (int j = 0; j < 4; j++) o[i][j] = 0.f;
    float m0 = -1e30f, m1 = -1e30f, l0 = 0.f, l1 = 0.f;

    for (int jt = 0; jt < 64; jt++) {
        const int p = jt & 1;
        __syncthreads();
        if (jt < 63) { fill_kv(smb, Kg, Vg, jt + 1, p ^ 1, tid); cp_commit(); cp_wait<1>(); }
        else         { cp_wait<0>(); }
        __syncthreads();

        const __half* Ksb = smh + KOFF(p);
        const __half* Vsb = smh + VOFF(p);

        // S = Q K^T
        float s[8][4];
        #pragma unroll
        for (int i = 0; i < 8; i++)
            #pragma unroll
            for (int j2 = 0; j2 < 4; j2++) s[i][j2] = 0.f;

        #pragma unroll
        for (int kt = 0; kt < 4; kt++) {
            #pragma unroll
            for (int nt = 0; nt < 8; nt++) {
                uint32_t bb[2];
                bb[0] = *(const uint32_t*)&Ksb[(size_t)(nt * 8 + lr) * 72 + kt * 16 + 2 * lc];
                bb[1] = *(const uint32_t*)&Ksb[(size_t)(nt * 8 + lr) * 72 + kt * 16 + 2 * lc + 8];
                mma16(s[nt], qf[kt], bb);
            }
        }

        // Online softmax (same statement order as prior rounds)
        float mx0 = s[0][0], mx1 = s[0][2];
        #pragma unroll
        for (int nt = 0; nt < 8; nt++) {
            mx0 = fmaxf(mx0, fmaxf(s[nt][0], s[nt][1]));
            mx1 = fmaxf(mx1, fmaxf(s[nt][2], s[nt][3]));
        }
        mx0 = fmaxf(mx0, __shfl_xor_sync(0xffffffffu, mx0, 1));
        mx0 = fmaxf(mx0, __shfl_xor_sync(0xffffffffu, mx0, 2));
        mx1 = fmaxf(mx1, __shfl_xor_sync(0xffffffffu, mx1, 1));
        mx1 = fmaxf(mx1, __shfl_xor_sync(0xffffffffu, mx1, 2));
        float mn0 = fmaxf(m0, mx0), mn1 = fmaxf(m1, mx1);
        float f0 = __expf(m0 - mn0), f1 = __expf(m1 - mn1);
        float sum0 = 0.f, sum1 = 0.f;
        #pragma unroll
        for (int nt = 0; nt < 8; nt++) {
            s[nt][0] = __expf(s[nt][0] - mn0); sum0 += s[nt][0];
            s[nt][1] = __expf(s[nt][1] - mn0); sum0 += s[nt][1];
            s[nt][2] = __expf(s[nt][2] - mn1); sum1 += s[nt][2];
            s[nt][3] = __expf(s[nt][3] - mn1); sum1 += s[nt][3];
        }
        sum0 += __shfl_xor_sync(0xffffffffu, sum0, 1);
        sum0 += __shfl_xor_sync(0xffffffffu, sum0, 2);
        sum1 += __shfl_xor_sync(0xffffffffu, sum1, 1);
        sum1 += __shfl_xor_sync(0xffffffffu, sum1, 2);
        l0 = l0 * f0 + sum0;
        l1 = l1 * f1 + sum1;
        m0 = mn0; m1 = mn1;
        #pragma unroll
        for (int dt = 0; dt < 8; dt++) {
            o[dt][0] *= f0; o[dt][1] *= f0; o[dt][2] *= f1; o[dt][3] *= f1;
        }

        // O += P V : A-frag is exactly the accumulator layout, packed to f16x2.
        #pragma unroll
        for (int kt = 0; kt < 4; kt++) {
            uint32_t a[4];
            a[0] = packh2(s[2 * kt][0],     s[2 * kt][1]);
            a[1] = packh2(s[2 * kt][2],     s[2 * kt][3]);
            a[2] = packh2(s[2 * kt + 1][0], s[2 * kt + 1][1]);
            a[3] = packh2(s[2 * kt + 1][2], s[2 * kt + 1][3]);
            #pragma unroll
            for (int dt = 0; dt < 8; dt++) {
                uint32_t bb[2];
                bb[0] = *(const uint32_t*)&Vsb[(size_t)(dt * 8 + lr) * 72 + kt * 16 + 2 * lc];
                bb[1] = *(const uint32_t*)&Vsb[(size_t)(dt * 8 + lr) * 72 + kt * 16 + 2 * lc + 8];
                mma16(o[dt], a, bb);
            }
        }
    }

    float inv0 = 1.f / l0, inv1 = 1.f / l1;
    const int b = bh >> 3, h = bh & 7;
    const int srow0 = qt * 128 + rbase + lr;
    float* obase = g_attnout + (size_t)b * S_LEN * CCH + (size_t)h * DH;
    #pragma unroll
    for (int dt = 0; dt < 8; dt++) {
        int d = dt * 8 + 2 * lc;
        *(float2*)(obase + (size_t)srow0 * CCH + d) =
            make_float2(o[dt][0] * inv0, o[dt][1] * inv0);
        *(float2*)(obase + (size_t)(srow0 + 8) * CCH + d) =
            make_float2(o[dt][2] * inv1, o[dt][3] * inv1);
    }
}

// ============================================================
// Kernel 3: output projection + transpose store to [b][c][s]  (tf32, R7)
// ============================================================
__global__ __launch_bounds__(256) void oproj_kernel(
    const float* __restrict__ Wo, const float* __restrict__ bo, float* __restrict__ out)
{
    const int m0 = blockIdx.y * 128;
    const int n0 = blockIdx.x * 128;

    __shared__ float As[16][136];
    __shared__ float Bs[16][136];

    const int tid = threadIdx.x, lane = tid & 31, warp = tid >> 5;
    const int wm = warp >> 2, wn = warp & 3, lr = lane >> 2, lc = lane & 3;

    float acc[4][4][4];
    #pragma unroll
    for (int i = 0; i < 4; i++)
        #pragma unroll
        for (int j = 0; j < 4; j++)
            #pragma unroll
            for (int k = 0; k < 4; k++) acc[i][j][k] = 0.f;

    for (int kb = 0; kb < CCH; kb += 16) {
        #pragma unroll
        for (int i = 0; i < 2; i++) {
            int idx = tid + i * 256;
            int k4 = idx & 3, m = idx >> 2;
            float4 v = *(const float4*)(g_attnout + (size_t)(m0 + m) * CCH + kb + k4 * 4);
            As[k4 * 4 + 0][m] = f2tff(v.x);
            As[k4 * 4 + 1][m] = f2tff(v.y);
            As[k4 * 4 + 2][m] = f2tff(v.z);
            As[k4 * 4 + 3][m] = f2tff(v.w);
        }
        #pragma unroll
        for (int i = 0; i < 2; i++) {
            int idx = tid + i * 256;
            int k4 = idx & 3, n = idx >> 2;
            float4 v = *(const float4*)(Wo + (size_t)(n0 + n) * CCH + kb + k4 * 4);
            Bs[k4 * 4 + 0][n] = f2tff(v.x);
            Bs[k4 * 4 + 1][n] = f2tff(v.y);
            Bs[k4 * 4 + 2][n] = f2tff(v.z);
            Bs[k4 * 4 + 3][n] = f2tff(v.w);
        }
        __syncthreads();

        #pragma unroll
        for (int kk = 0; kk < 16; kk += 8) {
            uint32_t af[4][4];
            #pragma unroll
            for (int mt = 0; mt < 4; mt++) {
                int r = wm * 64 + mt * 16 + lr;
                af[mt][0] = __float_as_uint(As[kk + lc][r]);
                af[mt][1] = __float_as_uint(As[kk + lc][r + 8]);
                af[mt][2] = __float_as_uint(As[kk + 4 + lc][r]);
                af[mt][3] = __float_as_uint(As[kk + 4 + lc][r + 8]);
            }
            uint32_t bf[4][2];
            #pragma unroll
            for (int nt = 0; nt < 4; nt++) {
                int c = wn * 32 + nt * 8 + lr;
                bf[nt][0] = __float_as_uint(Bs[kk + lc][c]);
                bf[nt][1] = __float_as_uint(Bs[kk + 4 + lc][c]);
            }
            #pragma unroll
            for (int mt = 0; mt < 4; mt++)
                #pragma unroll
                for (int nt = 0; nt < 4; nt++)
                    mma8(acc[mt][nt], af[mt], bf[nt]);
        }
        __syncthreads();
    }

    #pragma unroll
    for (int mt = 0; mt < 4; mt++) {
        #pragma unroll
        for (int nt = 0; nt < 4; nt++) {
            int r = m0 + wm * 64 + mt * 16 + lr;
            int c = n0 + wn * 32 + nt * 8 + 2 * lc;
            int bb = r >> 12, ss = r & 4095;
            float bias0 = bo[c], bias1 = bo[c + 1];
            float* pc  = out + ((size_t)bb * CCH + c) * S_LEN;
            float* pc1 = pc + S_LEN;
            pc[ss]      = acc[mt][nt][0] + bias0;
            pc1[ss]     = acc[mt][nt][1] + bias1;
            pc[ss + 8]  = acc[mt][nt][2] + bias0;
            pc1[ss + 8] = acc[mt][nt][3] + bias1;
        }
    }
}

// ============================================================
extern "C" void kernel_launch(void* const* d_in, const int* in_sizes, int n_in,
                              void* d_out, int out_size)
{
    const float* x   = (const float*)d_in[0];
    const float* ctx = (const float*)d_in[1];
    const float* Wq  = (const float*)d_in[2];
    const float* bq  = (const float*)d_in[3];
    const float* Wk  = (const float*)d_in[4];
    const float* bk  = (const float*)d_in[5];
    const float* Wv  = (const float*)d_in[6];
    const float* bv  = (const float*)d_in[7];
    const float* Wo  = (const float*)d_in[8];
    const float* bo  = (const float*)d_in[9];
    float* out = (float*)d_out;

    cudaFuncSetAttribute(attn_kernel, cudaFuncAttributeMaxDynamicSharedMemorySize, SMEMA);

    qkv_kernel<<<dim3(4, 32, 6), 256>>>(x, ctx, Wq, bq, Wk, bk, Wv, bv);
    attn_kernel<<<dim3(32, 16), 256, SMEMA>>>();
    oproj_kernel<<<dim3(4, 64), 256>>>(Wo, bo, out);
}

// round 14
// speedup vs baseline: 1.8150x; 1.2357x over previous
#include <cuda_runtime.h>
#include <cuda_fp16.h>
#include <cstdint>

#define S_LEN 4096
#define CCH   512
#define NH    8
#define DH    64
#define BATCH 2

// Scratch (all fp16 except noted)
__device__ __half g_q[(size_t)BATCH * NH * S_LEN * DH];    // [bh][s][d], pre-scaled 1/8
__device__ __half g_k[(size_t)BATCH * NH * S_LEN * DH];    // [bh][s][d]
__device__ __half g_v[(size_t)BATCH * NH * S_LEN * DH];    // [bh][d][s] TRANSPOSED
__device__ __half g_attnout[(size_t)BATCH * S_LEN * CCH];  // [b*4096+s][e]
__device__ __half g_xh[4][S_LEN][CCH];                     // {x b0, x b1, ctx b0, ctx b1} [s][c]
__device__ __half g_wh[4][CCH * CCH];                      // Wq,Wk,Wv,Wo [n][k]

__device__ __forceinline__ uint32_t packh2(float lo, float hi) {
    uint32_t r; asm("cvt.rn.f16x2.f32 %0, %1, %2;" : "=r"(r) : "f"(hi), "f"(lo)); return r;
}
__device__ __forceinline__ void mma16(float d[4], const uint32_t a[4], const uint32_t b[2]) {
    asm volatile(
        "mma.sync.aligned.m16n8k16.row.col.f32.f16.f16.f32 "
        "{%0,%1,%2,%3}, {%4,%5,%6,%7}, {%8,%9}, {%0,%1,%2,%3};\n"
        : "+f"(d[0]), "+f"(d[1]), "+f"(d[2]), "+f"(d[3])
        : "r"(a[0]), "r"(a[1]), "r"(a[2]), "r"(a[3]), "r"(b[0]), "r"(b[1]));
}
__device__ __forceinline__ void cp_async16(uint32_t s, const void* g) {
    asm volatile("cp.async.cg.shared.global [%0], [%1], 16;\n" :: "r"(s), "l"(g));
}
__device__ __forceinline__ void cp_commit() { asm volatile("cp.async.commit_group;\n"); }
template<int N> __device__ __forceinline__ void cp_wait() {
    asm volatile("cp.async.wait_group %0;\n" :: "n"(N));
}

// ============================================================
// Prepass 1: transpose-convert x/ctx -> g_xh[z][s][c] fp16
// ============================================================
__global__ __launch_bounds__(256) void prep_xh(const float* __restrict__ x,
                                               const float* __restrict__ ctx) {
    __shared__ float t[32][33];
    const int z = blockIdx.z;
    const float* src = (z < 2 ? x : ctx) + (size_t)(z & 1) * CCH * S_LEN;
    const int c0 = blockIdx.y * 32, s0 = blockIdx.x * 32;
    const int tx = threadIdx.x & 31, ty = threadIdx.x >> 5;
    #pragma unroll
    for (int i = 0; i < 32; i += 8)
        t[ty + i][tx] = src[(size_t)(c0 + ty + i) * S_LEN + s0 + tx];
    __syncthreads();
    #pragma unroll
    for (int i = 0; i < 32; i += 8)
        g_xh[z][s0 + ty + i][c0 + tx] = __float2half_rn(t[tx][ty + i]);
}

// Prepass 2: convert W's -> fp16
__global__ __launch_bounds__(256) void prep_wh(const float* __restrict__ Wq,
                                               const float* __restrict__ Wk,
                                               const float* __restrict__ Wv,
                                               const float* __restrict__ Wo) {
    const int m = blockIdx.y;
    const float* src = (m == 0) ? Wq : (m == 1) ? Wk : (m == 2) ? Wv : Wo;
    int i = blockIdx.x * 256 + threadIdx.x;   // float4 index (65536/matrix)
    float4 v = ((const float4*)src)[i];
    uint2 o; o.x = packh2(v.x, v.y); o.y = packh2(v.z, v.w);
    ((uint2*)&g_wh[m][0])[i] = o;
}

// ============================================================
// fp16 GEMM core: 128m x 128n x (K=512, BK=32), double-buffered cp.async.
// A rows = m (K-major), B rows = n (K-major). smem stride 40 halves.
// ============================================================
#define GST (128 * 40)   // halves per stage per operand

__device__ __forceinline__ void g_fill(uint32_t sa, uint32_t sb,
                                       const __half* Ag, const __half* Bg,
                                       int kb, int tid) {
    #pragma unroll
    for (int i = 0; i < 2; i++) {
        int idx = tid + i * 256;          // 0..511
        int row = idx >> 2, c8 = idx & 3;
        cp_async16(sa + (uint32_t)(row * 40 + c8 * 8) * 2, Ag + (size_t)row * CCH + kb + c8 * 8);
        cp_async16(sb + (uint32_t)(row * 40 + c8 * 8) * 2, Bg + (size_t)row * CCH + kb + c8 * 8);
    }
}

// computes acc[mt][nt][4]; smh points at {A0,B0,A1,B1} stage layout
struct GemmSmem { __half a[2][GST]; __half b[2][GST]; };

__device__ __forceinline__ void g_gemm(float acc[4][4][4], GemmSmem* S,
                                       const __half* Ag, const __half* Bg,
                                       int tid, int lane, int warp) {
    const int wm = warp >> 2, wn = warp & 3, lr = lane >> 2, lc = lane & 3;
    uint32_t smb = (uint32_t)__cvta_generic_to_shared(S);
    const uint32_t sa0 = smb, sb0 = smb + 2 * 2 * GST;   // bytes: a at 0, b at 2*GST*2*... 
    // layout: a[2][GST] then b[2][GST]; a[p] at p*GST*2 bytes, b[p] at (2*GST + p*GST)*2
    g_fill(smb + 0, smb + (uint32_t)(2 * GST) * 2, Ag, Bg, 0, tid);
    cp_commit();
    for (int s = 0; s < 16; s++) {
        const int p = s & 1;
        __syncthreads();
        if (s < 15) {
            const int q = p ^ 1;
            g_fill(smb + (uint32_t)(q * GST) * 2, smb + (uint32_t)((2 + q) * GST) * 2,
                   Ag, Bg, (s + 1) * 32, tid);
            cp_commit();
            cp_wait<1>();
        } else cp_wait<0>();
        __syncthreads();

        const __half* Ap = S->a[p];
        const __half* Bp = S->b[p];
        #pragma unroll
        for (int kk = 0; kk < 32; kk += 16) {
            uint32_t af[4][4];
            #pragma unroll
            for (int mt = 0; mt < 4; mt++) {
                int m = wm * 64 + mt * 16 + lr;
                af[mt][0] = *(const uint32_t*)&Ap[(size_t)m * 40 + kk + 2 * lc];
                af[mt][1] = *(const uint32_t*)&Ap[(size_t)(m + 8) * 40 + kk + 2 * lc];
                af[mt][2] = *(const uint32_t*)&Ap[(size_t)m * 40 + kk + 2 * lc + 8];
                af[mt][3] = *(const uint32_t*)&Ap[(size_t)(m + 8) * 40 + kk + 2 * lc + 8];
            }
            uint32_t bf[4][2];
            #pragma unroll
            for (int nt = 0; nt < 4; nt++) {
                int n = wn * 32 + nt * 8 + lr;
                bf[nt][0] = *(const uint32_t*)&Bp[(size_t)n * 40 + kk + 2 * lc];
                bf[nt][1] = *(const uint32_t*)&Bp[(size_t)n * 40 + kk + 2 * lc + 8];
            }
            #pragma unroll
            for (int mt = 0; mt < 4; mt++)
                #pragma unroll
                for (int nt = 0; nt < 4; nt++)
                    mma16(acc[mt][nt], af[mt], bf[nt]);
        }
    }
}

// ============================================================
// Kernel 1: QKV projections (fp16 GEMM; epilogue stores fp16, V transposed)
// ============================================================
__global__ __launch_bounds__(256) void qkv2(const float* __restrict__ bq,
                                            const float* __restrict__ bk,
                                            const float* __restrict__ bv) {
    __shared__ GemmSmem S;
    const int tid = threadIdx.x, lane = tid & 31, warp = tid >> 5;
    const int wm = warp >> 2, wn = warp & 3, lr = lane >> 2, lc = lane & 3;

    const int proj = blockIdx.z >> 1;
    const int b    = blockIdx.z & 1;
    const int s0   = blockIdx.y * 128;
    const int e0   = blockIdx.x * 128;
    const __half* Ag  = &g_xh[(proj == 0 ? 0 : 2) + b][s0][0];
    const __half* Bg  = &g_wh[proj][0] + (size_t)e0 * CCH;
    const float* bias = (proj == 0) ? bq : (proj == 1) ? bk : bv;
    __half* outbuf    = (proj == 0) ? g_q : (proj == 1) ? g_k : g_v;
    const float scale = (proj == 0) ? 0.125f : 1.0f;
    const bool isV    = (proj == 2);

    float acc[4][4][4];
    #pragma unroll
    for (int i = 0; i < 4; i++)
        #pragma unroll
        for (int j = 0; j < 4; j++)
            #pragma unroll
            for (int k = 0; k < 4; k++) acc[i][j][k] = 0.f;

    g_gemm(acc, &S, Ag, Bg, tid, lane, warp);

    #pragma unroll
    for (int mt = 0; mt < 4; mt++) {
        #pragma unroll
        for (int nt = 0; nt < 4; nt++) {
            int r = s0 + wm * 64 + mt * 16 + lr;
            int c = e0 + wn * 32 + nt * 8 + 2 * lc;
            float b0 = bias[c], b1 = bias[c + 1];
            int h = c >> 6, d = c & 63;
            float v0 = (acc[mt][nt][0] + b0) * scale;
            float v1 = (acc[mt][nt][1] + b1) * scale;
            float v2 = (acc[mt][nt][2] + b0) * scale;
            float v3 = (acc[mt][nt][3] + b1) * scale;
            if (!isV) {
                __half* qb = outbuf + ((size_t)(b * NH + h) * S_LEN) * DH + d;
                *(uint32_t*)(qb + (size_t)r * DH)       = packh2(v0, v1);
                *(uint32_t*)(qb + (size_t)(r + 8) * DH) = packh2(v2, v3);
            } else {
                __half* vb = outbuf + ((size_t)(b * NH + h) * DH) * S_LEN;
                vb[(size_t)(d    ) * S_LEN + r]     = __float2half_rn(v0);
                vb[(size_t)(d + 1) * S_LEN + r]     = __float2half_rn(v1);
                vb[(size_t)(d    ) * S_LEN + r + 8] = __float2half_rn(v2);
                vb[(size_t)(d + 1) * S_LEN + r + 8] = __float2half_rn(v3);
            }
        }
    }
}

// ============================================================
// Kernel 2: flash attention, fp16 mma (R12; epilogue stores fp16 attnout)
// smem (halves): Q[128][72] | K0,K1[64][72] | V0,V1[64][72]
// ============================================================
#define QH   (128 * 72)
#define KOFF(p) (QH + (p) * (64 * 72))
#define VOFF(p) (QH + 2 * 64 * 72 + (p) * (64 * 72))
#define SMEMA ((QH + 4 * 64 * 72) * 2)

__device__ __forceinline__ void fill_kv(uint32_t smb, const __half* Kg, const __half* Vg,
                                        int jt, int p, int tid)
{
    uint32_t kb = smb + KOFF(p) * 2;
    uint32_t vb = smb + VOFF(p) * 2;
    #pragma unroll
    for (int i = 0; i < 2; i++) {
        int idx = tid + i * 256;
        int j = idx >> 3, c8 = idx & 7;
        cp_async16(kb + (uint32_t)(j * 72 + c8 * 8) * 2, Kg + ((size_t)jt * 64 + j) * DH + c8 * 8);
        cp_async16(vb + (uint32_t)(j * 72 + c8 * 8) * 2, Vg + (size_t)j * S_LEN + jt * 64 + c8 * 8);
    }
}

__global__ __launch_bounds__(256) void attn_kernel()
{
    extern __shared__ __half smh[];
    const int qt = blockIdx.x, bh = blockIdx.y;
    const int tid = threadIdx.x, lane = tid & 31, warp = tid >> 5;
    const int lr = lane >> 2, lc = lane & 3;
    const int rbase = warp * 16;

    const __half* Qg = g_q + (size_t)bh * S_LEN * DH + (size_t)qt * 128 * DH;
    const __half* Kg = g_k + (size_t)bh * S_LEN * DH;
    const __half* Vg = g_v + (size_t)bh * S_LEN * DH;   // [d][s]

    uint32_t smb = (uint32_t)__cvta_generic_to_shared(smh);

    #pragma unroll
    for (int i = 0; i < 4; i++) {
        int idx = tid + i * 256;
        int j = idx >> 3, c8 = idx & 7;
        cp_async16(smb + (uint32_t)(j * 72 + c8 * 8) * 2, Qg + (size_t)j * DH + c8 * 8);
    }
    cp_commit();
    fill_kv(smb, Kg, Vg, 0, 0, tid);
    cp_commit();
    cp_wait<1>();
    __syncthreads();

    uint32_t qf[4][4];
    #pragma unroll
    for (int kt = 0; kt < 4; kt++) {
        int r = rbase + lr;
        qf[kt][0] = *(const uint32_t*)&smh[(size_t)r * 72 + kt * 16 + 2 * lc];
        qf[kt][1] = *(const uint32_t*)&smh[(size_t)(r + 8) * 72 + kt * 16 + 2 * lc];
        qf[kt][2] = *(const uint32_t*)&smh[(size_t)r * 72 + kt * 16 + 2 * lc + 8];
        qf[kt][3] = *(const uint32_t*)&smh[(size_t)(r + 8) * 72 + kt * 16 + 2 * lc + 8];
    }

    float o[8][4];
    #pragma unroll
    for (int i = 0; i < 8; i++)
        #pragma unroll
        for (int j = 0; j < 4; j++) o[i][j] = 0.f;
    float m0 = -1e30f, m1 = -1e30f, l0 = 0.f, l1 = 0.f;

    for (int jt = 0; jt < 64; jt++) {
        const int p = jt & 1;
        __syncthreads();
        if (jt < 63) { fill_kv(smb, Kg, Vg, jt + 1, p ^ 1, tid); cp_commit(); cp_wait<1>(); }
        else         { cp_wait<0>(); }
        __syncthreads();

        const __half* Ksb = smh + KOFF(p);
        const __half* Vsb = smh + VOFF(p);

        float s[8][4];
        #pragma unroll
        for (int i = 0; i < 8; i++)
            #pragma unroll
            for (int j2 = 0; j2 < 4; j2++) s[i][j2] = 0.f;

        #pragma unroll
        for (int kt = 0; kt < 4; kt++) {
            #pragma unroll
            for (int nt = 0; nt < 8; nt++) {
                uint32_t bb[2];
                bb[0] = *(const uint32_t*)&Ksb[(size_t)(nt * 8 + lr) * 72 + kt * 16 + 2 * lc];
                bb[1] = *(const uint32_t*)&Ksb[(size_t)(nt * 8 + lr) * 72 + kt * 16 + 2 * lc + 8];
                mma16(s[nt], qf[kt], bb);
            }
        }

        float mx0 = s[0][0], mx1 = s[0][2];
        #pragma unroll
        for (int nt = 0; nt < 8; nt++) {
            mx0 = fmaxf(mx0, fmaxf(s[nt][0], s[nt][1]));
            mx1 = fmaxf(mx1, fmaxf(s[nt][2], s[nt][3]));
        }
        mx0 = fmaxf(mx0, __shfl_xor_sync(0xffffffffu, mx0, 1));
        mx0 = fmaxf(mx0, __shfl_xor_sync(0xffffffffu, mx0, 2));
        mx1 = fmaxf(mx1, __shfl_xor_sync(0xffffffffu, mx1, 1));
        mx1 = fmaxf(mx1, __shfl_xor_sync(0xffffffffu, mx1, 2));
        float mn0 = fmaxf(m0, mx0), mn1 = fmaxf(m1, mx1);
        float f0 = __expf(m0 - mn0), f1 = __expf(m1 - mn1);
        float sum0 = 0.f, sum1 = 0.f;
        #pragma unroll
        for (int nt = 0; nt < 8; nt++) {
            s[nt][0] = __expf(s[nt][0] - mn0); sum0 += s[nt][0];
            s[nt][1] = __expf(s[nt][1] - mn0); sum0 += s[nt][1];
            s[nt][2] = __expf(s[nt][2] - mn1); sum1 += s[nt][2];
            s[nt][3] = __expf(s[nt][3] - mn1); sum1 += s[nt][3];
        }
        sum0 += __shfl_xor_sync(0xffffffffu, sum0, 1);
        sum0 += __shfl_xor_sync(0xffffffffu, sum0, 2);
        sum1 += __shfl_xor_sync(0xffffffffu, sum1, 1);
        sum1 += __shfl_xor_sync(0xffffffffu, sum1, 2);
        l0 = l0 * f0 + sum0;
        l1 = l1 * f1 + sum1;
        m0 = mn0; m1 = mn1;
        #pragma unroll
        for (int dt = 0; dt < 8; dt++) {
            o[dt][0] *= f0; o[dt][1] *= f0; o[dt][2] *= f1; o[dt][3] *= f1;
        }

        #pragma unroll
        for (int kt = 0; kt < 4; kt++) {
            uint32_t a[4];
            a[0] = packh2(s[2 * kt][0],     s[2 * kt][1]);
            a[1] = packh2(s[2 * kt][2],     s[2 * kt][3]);
            a[2] = packh2(s[2 * kt + 1][0], s[2 * kt + 1][1]);
            a[3] = packh2(s[2 * kt + 1][2], s[2 * kt + 1][3]);
            #pragma unroll
            for (int dt = 0; dt < 8; dt++) {
                uint32_t bb[2];
                bb[0] = *(const uint32_t*)&Vsb[(size_t)(dt * 8 + lr) * 72 + kt * 16 + 2 * lc];
                bb[1] = *(const uint32_t*)&Vsb[(size_t)(dt * 8 + lr) * 72 + kt * 16 + 2 * lc + 8];
                mma16(o[dt], a, bb);
            }
        }
    }

    float inv0 = 1.f / l0, inv1 = 1.f / l1;
    const int b = bh >> 3, h = bh & 7;
    const int srow0 = qt * 128 + rbase + lr;
    __half* obase = g_attnout + (size_t)b * S_LEN * CCH + (size_t)h * DH;
    #pragma unroll
    for (int dt = 0; dt < 8; dt++) {
        int d = dt * 8 + 2 * lc;
        *(uint32_t*)(obase + (size_t)srow0 * CCH + d) =
            packh2(o[dt][0] * inv0, o[dt][1] * inv0);
        *(uint32_t*)(obase + (size_t)(srow0 + 8) * CCH + d) =
            packh2(o[dt][2] * inv1, o[dt][3] * inv1);
    }
}

// ============================================================
// Kernel 3: output projection (fp16 GEMM) + transpose store to [b][c][s]
// ============================================================
__global__ __launch_bounds__(256) void oproj2(const float* __restrict__ bo,
                                              float* __restrict__ out) {
    __shared__ GemmSmem S;
    const int tid = threadIdx.x, lane = tid & 31, warp = tid >> 5;
    const int wm = warp >> 2, wn = warp & 3, lr = lane >> 2, lc = lane & 3;

    const int m0 = blockIdx.y * 128;   // over 8192
    const int n0 = blockIdx.x * 128;   // over 512
    const __half* Ag = g_attnout + (size_t)m0 * CCH;
    const __half* Bg = &g_wh[3][0] + (size_t)n0 * CCH;

    float acc[4][4][4];
    #pragma unroll
    for (int i = 0; i < 4; i++)
        #pragma unroll
        for (int j = 0; j < 4; j++)
            #pragma unroll
            for (int k = 0; k < 4; k++) acc[i][j][k] = 0.f;

    g_gemm(acc, &S, Ag, Bg, tid, lane, warp);

    #pragma unroll
    for (int mt = 0; mt < 4; mt++) {
        #pragma unroll
        for (int nt = 0; nt < 4; nt++) {
            int r = m0 + wm * 64 + mt * 16 + lr;
            int c = n0 + wn * 32 + nt * 8 + 2 * lc;
            int bb = r >> 12, ss = r & 4095;
            float bias0 = bo[c], bias1 = bo[c + 1];
            float* pc  = out + ((size_t)bb * CCH + c) * S_LEN;
            float* pc1 = pc + S_LEN;
            pc[ss]      = acc[mt][nt][0] + bias0;
            pc1[ss]     = acc[mt][nt][1] + bias1;
            pc[ss + 8]  = acc[mt][nt][2] + bias0;
            pc1[ss + 8] = acc[mt][nt][3] + bias1;
        }
    }
}

// ============================================================
extern "C" void kernel_launch(void* const* d_in, const int* in_sizes, int n_in,
                              void* d_out, int out_size)
{
    const float* x   = (const float*)d_in[0];
    const float* ctx = (const float*)d_in[1];
    const float* Wq  = (const float*)d_in[2];
    const float* bq  = (const float*)d_in[3];
    const float* Wk  = (const float*)d_in[4];
    const float* bk  = (const float*)d_in[5];
    const float* Wv  = (const float*)d_in[6];
    const float* bv  = (const float*)d_in[7];
    const float* Wo  = (const float*)d_in[8];
    const float* bo  = (const float*)d_in[9];
    float* out = (float*)d_out;

    cudaFuncSetAttribute(attn_kernel, cudaFuncAttributeMaxDynamicSharedMemorySize, SMEMA);

    prep_xh<<<dim3(128, 16, 4), 256>>>(x, ctx);
    prep_wh<<<dim3(256, 4), 256>>>(Wq, Wk, Wv, Wo);
    qkv2<<<dim3(4, 32, 6), 256>>>(bq, bk, bv);
    attn_kernel<<<dim3(32, 16), 256, SMEMA>>>();
    oproj2<<<dim3(4, 64), 256>>>(bo, out);
}

// round 15
// speedup vs baseline: 1.9323x; 1.0646x over previous
#include <cuda_runtime.h>
#include <cuda_fp16.h>
#include <cstdint>

#define S_LEN 4096
#define CCH   512
#define NH    8
#define DH    64
#define BATCH 2

// Scratch (all fp16 except noted)
__device__ __half g_q[(size_t)BATCH * NH * S_LEN * DH];    // [bh][s][d], pre-scaled 1/8
__device__ __half g_k[(size_t)BATCH * NH * S_LEN * DH];    // [bh][s][d]
__device__ __half g_v[(size_t)BATCH * NH * S_LEN * DH];    // [bh][d][s] TRANSPOSED
__device__ __half g_attnout[(size_t)BATCH * S_LEN * CCH];  // [b*4096+s][e]
__device__ __half g_xh[4][S_LEN][CCH];                     // {x b0, x b1, ctx b0, ctx b1} [s][c]
__device__ __half g_wh[4][CCH * CCH];                      // Wq,Wk,Wv,Wo [n][k]

__device__ __forceinline__ uint32_t packh2(float lo, float hi) {
    uint32_t r; asm("cvt.rn.f16x2.f32 %0, %1, %2;" : "=r"(r) : "f"(hi), "f"(lo)); return r;
}
__device__ __forceinline__ void mma16(float d[4], const uint32_t a[4], const uint32_t b[2]) {
    asm volatile(
        "mma.sync.aligned.m16n8k16.row.col.f32.f16.f16.f32 "
        "{%0,%1,%2,%3}, {%4,%5,%6,%7}, {%8,%9}, {%0,%1,%2,%3};\n"
        : "+f"(d[0]), "+f"(d[1]), "+f"(d[2]), "+f"(d[3])
        : "r"(a[0]), "r"(a[1]), "r"(a[2]), "r"(a[3]), "r"(b[0]), "r"(b[1]));
}
__device__ __forceinline__ void cp_async16(uint32_t s, const void* g) {
    asm volatile("cp.async.cg.shared.global [%0], [%1], 16;\n" :: "r"(s), "l"(g));
}
__device__ __forceinline__ void cp_commit() { asm volatile("cp.async.commit_group;\n"); }
template<int N> __device__ __forceinline__ void cp_wait() {
    asm volatile("cp.async.wait_group %0;\n" :: "n"(N));
}
__device__ __forceinline__ void ldsm4(uint32_t r[4], uint32_t addr) {
    asm volatile("ldmatrix.sync.aligned.m8n8.x4.shared.b16 {%0,%1,%2,%3}, [%4];"
        : "=r"(r[0]), "=r"(r[1]), "=r"(r[2]), "=r"(r[3]) : "r"(addr));
}

// ============================================================
// Prepass 1: transpose-convert x/ctx -> g_xh[z][s][c] fp16
// ============================================================
__global__ __launch_bounds__(256) void prep_xh(const float* __restrict__ x,
                                               const float* __restrict__ ctx) {
    __shared__ float t[32][33];
    const int z = blockIdx.z;
    const float* src = (z < 2 ? x : ctx) + (size_t)(z & 1) * CCH * S_LEN;
    const int c0 = blockIdx.y * 32, s0 = blockIdx.x * 32;
    const int tx = threadIdx.x & 31, ty = threadIdx.x >> 5;
    #pragma unroll
    for (int i = 0; i < 32; i += 8)
        t[ty + i][tx] = src[(size_t)(c0 + ty + i) * S_LEN + s0 + tx];
    __syncthreads();
    #pragma unroll
    for (int i = 0; i < 32; i += 8)
        g_xh[z][s0 + ty + i][c0 + tx] = __float2half_rn(t[tx][ty + i]);
}

// Prepass 2: convert W's -> fp16
__global__ __launch_bounds__(256) void prep_wh(const float* __restrict__ Wq,
                                               const float* __restrict__ Wk,
                                               const float* __restrict__ Wv,
                                               const float* __restrict__ Wo) {
    const int m = blockIdx.y;
    const float* src = (m == 0) ? Wq : (m == 1) ? Wk : (m == 2) ? Wv : Wo;
    int i = blockIdx.x * 256 + threadIdx.x;   // float4 index (65536/matrix)
    float4 v = ((const float4*)src)[i];
    uint2 o; o.x = packh2(v.x, v.y); o.y = packh2(v.z, v.w);
    ((uint2*)&g_wh[m][0])[i] = o;
}

// ============================================================
// fp16 GEMM core: 128m x 128n x (K=512, BK=32), double-buffered cp.async.
// A rows = m (K-major), B rows = n (K-major). smem stride 40 halves.
// ============================================================
#define GST (128 * 40)   // halves per stage per operand

__device__ __forceinline__ void g_fill(uint32_t sa, uint32_t sb,
                                       const __half* Ag, const __half* Bg,
                                       int kb, int tid) {
    #pragma unroll
    for (int i = 0; i < 2; i++) {
        int idx = tid + i * 256;          // 0..511
        int row = idx >> 2, c8 = idx & 3;
        cp_async16(sa + (uint32_t)(row * 40 + c8 * 8) * 2, Ag + (size_t)row * CCH + kb + c8 * 8);
        cp_async16(sb + (uint32_t)(row * 40 + c8 * 8) * 2, Bg + (size_t)row * CCH + kb + c8 * 8);
    }
}

struct GemmSmem { __half a[2][GST]; __half b[2][GST]; };

__device__ __forceinline__ void g_gemm(float acc[4][4][4], GemmSmem* S,
                                       const __half* Ag, const __half* Bg,
                                       int tid, int lane, int warp) {
    const int wm = warp >> 2, wn = warp & 3, lr = lane >> 2, lc = lane & 3;
    uint32_t smb = (uint32_t)__cvta_generic_to_shared(S);
    g_fill(smb + 0, smb + (uint32_t)(2 * GST) * 2, Ag, Bg, 0, tid);
    cp_commit();
    for (int s = 0; s < 16; s++) {
        const int p = s & 1;
        __syncthreads();
        if (s < 15) {
            const int q = p ^ 1;
            g_fill(smb + (uint32_t)(q * GST) * 2, smb + (uint32_t)((2 + q) * GST) * 2,
                   Ag, Bg, (s + 1) * 32, tid);
            cp_commit();
            cp_wait<1>();
        } else cp_wait<0>();
        __syncthreads();

        const __half* Ap = S->a[p];
        const __half* Bp = S->b[p];
        #pragma unroll
        for (int kk = 0; kk < 32; kk += 16) {
            uint32_t af[4][4];
            #pragma unroll
            for (int mt = 0; mt < 4; mt++) {
                int m = wm * 64 + mt * 16 + lr;
                af[mt][0] = *(const uint32_t*)&Ap[(size_t)m * 40 + kk + 2 * lc];
                af[mt][1] = *(const uint32_t*)&Ap[(size_t)(m + 8) * 40 + kk + 2 * lc];
                af[mt][2] = *(const uint32_t*)&Ap[(size_t)m * 40 + kk + 2 * lc + 8];
                af[mt][3] = *(const uint32_t*)&Ap[(size_t)(m + 8) * 40 + kk + 2 * lc + 8];
            }
            uint32_t bf[4][2];
            #pragma unroll
            for (int nt = 0; nt < 4; nt++) {
                int n = wn * 32 + nt * 8 + lr;
                bf[nt][0] = *(const uint32_t*)&Bp[(size_t)n * 40 + kk + 2 * lc];
                bf[nt][1] = *(const uint32_t*)&Bp[(size_t)n * 40 + kk + 2 * lc + 8];
            }
            #pragma unroll
            for (int mt = 0; mt < 4; mt++)
                #pragma unroll
                for (int nt = 0; nt < 4; nt++)
                    mma16(acc[mt][nt], af[mt], bf[nt]);
        }
    }
}

// ============================================================
// Kernel 1: QKV projections (fp16 GEMM; epilogue stores fp16, V transposed)
// ============================================================
__global__ __launch_bounds__(256) void qkv2(const float* __restrict__ bq,
                                            const float* __restrict__ bk,
                                            const float* __restrict__ bv) {
    __shared__ GemmSmem S;
    const int tid = threadIdx.x, lane = tid & 31, warp = tid >> 5;
    const int wm = warp >> 2, wn = warp & 3, lr = lane >> 2, lc = lane & 3;

    const int proj = blockIdx.z >> 1;
    const int b    = blockIdx.z & 1;
    const int s0   = blockIdx.y * 128;
    const int e0   = blockIdx.x * 128;
    const __half* Ag  = &g_xh[(proj == 0 ? 0 : 2) + b][s0][0];
    const __half* Bg  = &g_wh[proj][0] + (size_t)e0 * CCH;
    const float* bias = (proj == 0) ? bq : (proj == 1) ? bk : bv;
    __half* outbuf    = (proj == 0) ? g_q : (proj == 1) ? g_k : g_v;
    const float scale = (proj == 0) ? 0.125f : 1.0f;
    const bool isV    = (proj == 2);

    float acc[4][4][4];
    #pragma unroll
    for (int i = 0; i < 4; i++)
        #pragma unroll
        for (int j = 0; j < 4; j++)
            #pragma unroll
            for (int k = 0; k < 4; k++) acc[i][j][k] = 0.f;

    g_gemm(acc, &S, Ag, Bg, tid, lane, warp);

    #pragma unroll
    for (int mt = 0; mt < 4; mt++) {
        #pragma unroll
        for (int nt = 0; nt < 4; nt++) {
            int r = s0 + wm * 64 + mt * 16 + lr;
            int c = e0 + wn * 32 + nt * 8 + 2 * lc;
            float b0 = bias[c], b1 = bias[c + 1];
            int h = c >> 6, d = c & 63;
            float v0 = (acc[mt][nt][0] + b0) * scale;
            float v1 = (acc[mt][nt][1] + b1) * scale;
            float v2 = (acc[mt][nt][2] + b0) * scale;
            float v3 = (acc[mt][nt][3] + b1) * scale;
            if (!isV) {
                __half* qb = outbuf + ((size_t)(b * NH + h) * S_LEN) * DH + d;
                *(uint32_t*)(qb + (size_t)r * DH)       = packh2(v0, v1);
                *(uint32_t*)(qb + (size_t)(r + 8) * DH) = packh2(v2, v3);
            } else {
                __half* vb = outbuf + ((size_t)(b * NH + h) * DH) * S_LEN;
                vb[(size_t)(d    ) * S_LEN + r]     = __float2half_rn(v0);
                vb[(size_t)(d + 1) * S_LEN + r]     = __float2half_rn(v1);
                vb[(size_t)(d    ) * S_LEN + r + 8] = __float2half_rn(v2);
                vb[(size_t)(d + 1) * S_LEN + r + 8] = __float2half_rn(v3);
            }
        }
    }
}

// ============================================================
// Kernel 2: flash attention, fp16 mma + ldmatrix fragments.
// smem (halves): Q[128][72] | K0,K1[64][72] | V0,V1[64][72]
// ============================================================
#define QH   (128 * 72)
#define KOFF(p) (QH + (p) * (64 * 72))
#define VOFF(p) (QH + 2 * 64 * 72 + (p) * (64 * 72))
#define SMEMA ((QH + 4 * 64 * 72) * 2)

__device__ __forceinline__ void fill_kv(uint32_t smb, const __half* Kg, const __half* Vg,
                                        int jt, int p, int tid)
{
    uint32_t kb = smb + KOFF(p) * 2;
    uint32_t vb = smb + VOFF(p) * 2;
    #pragma unroll
    for (int i = 0; i < 2; i++) {
        int idx = tid + i * 256;
        int j = idx >> 3, c8 = idx & 7;
        cp_async16(kb + (uint32_t)(j * 72 + c8 * 8) * 2, Kg + ((size_t)jt * 64 + j) * DH + c8 * 8);
        cp_async16(vb + (uint32_t)(j * 72 + c8 * 8) * 2, Vg + (size_t)j * S_LEN + jt * 64 + c8 * 8);
    }
}

__global__ __launch_bounds__(256) void attn_kernel()
{
    extern __shared__ __half smh[];
    const int qt = blockIdx.x, bh = blockIdx.y;
    const int tid = threadIdx.x, lane = tid & 31, warp = tid >> 5;
    const int lr = lane >> 2, lc = lane & 3;
    const int rbase = warp * 16;

    const __half* Qg = g_q + (size_t)bh * S_LEN * DH + (size_t)qt * 128 * DH;
    const __half* Kg = g_k + (size_t)bh * S_LEN * DH;
    const __half* Vg = g_v + (size_t)bh * S_LEN * DH;   // [d][s]

    uint32_t smb = (uint32_t)__cvta_generic_to_shared(smh);

    // ldmatrix B-tile per-thread offset: lane group g8 selects tile
    // {nt-even/klo, nt-even/khi, nt-odd/klo, nt-odd/khi}
    const int g8 = lane >> 3, r8 = lane & 7;
    const uint32_t tile_off = (uint32_t)((((g8 >> 1) << 3) + r8) * 72 + ((g8 & 1) << 3)) * 2;

    #pragma unroll
    for (int i = 0; i < 4; i++) {
        int idx = tid + i * 256;
        int j = idx >> 3, c8 = idx & 7;
        cp_async16(smb + (uint32_t)(j * 72 + c8 * 8) * 2, Qg + (size_t)j * DH + c8 * 8);
    }
    cp_commit();
    fill_kv(smb, Kg, Vg, 0, 0, tid);
    cp_commit();
    cp_wait<1>();
    __syncthreads();

    uint32_t qf[4][4];
    #pragma unroll
    for (int kt = 0; kt < 4; kt++) {
        int r = rbase + lr;
        qf[kt][0] = *(const uint32_t*)&smh[(size_t)r * 72 + kt * 16 + 2 * lc];
        qf[kt][1] = *(const uint32_t*)&smh[(size_t)(r + 8) * 72 + kt * 16 + 2 * lc];
        qf[kt][2] = *(const uint32_t*)&smh[(size_t)r * 72 + kt * 16 + 2 * lc + 8];
        qf[kt][3] = *(const uint32_t*)&smh[(size_t)(r + 8) * 72 + kt * 16 + 2 * lc + 8];
    }

    float o[8][4];
    #pragma unroll
    for (int i = 0; i < 8; i++)
        #pragma unroll
        for (int j = 0; j < 4; j++) o[i][j] = 0.f;
    float m0 = -1e30f, m1 = -1e30f, l0 = 0.f, l1 = 0.f;

    for (int jt = 0; jt < 64; jt++) {
        const int p = jt & 1;
        __syncthreads();
        if (jt < 63) { fill_kv(smb, Kg, Vg, jt + 1, p ^ 1, tid); cp_commit(); cp_wait<1>(); }
        else         { cp_wait<0>(); }
        __syncthreads();

        const uint32_t Kb = smb + KOFF(p) * 2 + tile_off;
        const uint32_t Vb = smb + VOFF(p) * 2 + tile_off;

        // S = Q K^T (ldmatrix x4: 4 tiles = {nt-pair} x {k-halves})
        float s[8][4];
        #pragma unroll
        for (int i = 0; i < 8; i++)
            #pragma unroll
            for (int j2 = 0; j2 < 4; j2++) s[i][j2] = 0.f;

        #pragma unroll
        for (int kt = 0; kt < 4; kt++) {
            #pragma unroll
            for (int np = 0; np < 4; np++) {
                uint32_t bb[4];
                ldsm4(bb, Kb + (uint32_t)((np * 16 * 72 + kt * 16) * 2));
                mma16(s[2 * np],     qf[kt], bb);
                mma16(s[2 * np + 1], qf[kt], bb + 2);
            }
        }

        // Online softmax (same statement order as R13)
        float mx0 = s[0][0], mx1 = s[0][2];
        #pragma unroll
        for (int nt = 0; nt < 8; nt++) {
            mx0 = fmaxf(mx0, fmaxf(s[nt][0], s[nt][1]));
            mx1 = fmaxf(mx1, fmaxf(s[nt][2], s[nt][3]));
        }
        mx0 = fmaxf(mx0, __shfl_xor_sync(0xffffffffu, mx0, 1));
        mx0 = fmaxf(mx0, __shfl_xor_sync(0xffffffffu, mx0, 2));
        mx1 = fmaxf(mx1, __shfl_xor_sync(0xffffffffu, mx1, 1));
        mx1 = fmaxf(mx1, __shfl_xor_sync(0xffffffffu, mx1, 2));
        float mn0 = fmaxf(m0, mx0), mn1 = fmaxf(m1, mx1);
        float f0 = __expf(m0 - mn0), f1 = __expf(m1 - mn1);
        float sum0 = 0.f, sum1 = 0.f;
        #pragma unroll
        for (int nt = 0; nt < 8; nt++) {
            s[nt][0] = __expf(s[nt][0] - mn0); sum0 += s[nt][0];
            s[nt][1] = __expf(s[nt][1] - mn0); sum0 += s[nt][1];
            s[nt][2] = __expf(s[nt][2] - mn1); sum1 += s[nt][2];
            s[nt][3] = __expf(s[nt][3] - mn1); sum1 += s[nt][3];
        }
        sum0 += __shfl_xor_sync(0xffffffffu, sum0, 1);
        sum0 += __shfl_xor_sync(0xffffffffu, sum0, 2);
        sum1 += __shfl_xor_sync(0xffffffffu, sum1, 1);
        sum1 += __shfl_xor_sync(0xffffffffu, sum1, 2);
        l0 = l0 * f0 + sum0;
        l1 = l1 * f1 + sum1;
        m0 = mn0; m1 = mn1;
        // Skip rescale when factors are exactly 1.0 (o*1.0f == o bitwise)
        if ((f0 != 1.f) | (f1 != 1.f)) {
            #pragma unroll
            for (int dt = 0; dt < 8; dt++) {
                o[dt][0] *= f0; o[dt][1] *= f0; o[dt][2] *= f1; o[dt][3] *= f1;
            }
        }

        // O += P V (A-frag = packed accumulators; B via ldmatrix from [d][s]-major V)
        #pragma unroll
        for (int kt = 0; kt < 4; kt++) {
            uint32_t a[4];
            a[0] = packh2(s[2 * kt][0],     s[2 * kt][1]);
            a[1] = packh2(s[2 * kt][2],     s[2 * kt][3]);
            a[2] = packh2(s[2 * kt + 1][0], s[2 * kt + 1][1]);
            a[3] = packh2(s[2 * kt + 1][2], s[2 * kt + 1][3]);
            #pragma unroll
            for (int dp = 0; dp < 4; dp++) {
                uint32_t bb[4];
                ldsm4(bb, Vb + (uint32_t)((dp * 16 * 72 + kt * 16) * 2));
                mma16(o[2 * dp],     a, bb);
                mma16(o[2 * dp + 1], a, bb + 2);
            }
        }
    }

    float inv0 = 1.f / l0, inv1 = 1.f / l1;
    const int b = bh >> 3, h = bh & 7;
    const int srow0 = qt * 128 + rbase + lr;
    __half* obase = g_attnout + (size_t)b * S_LEN * CCH + (size_t)h * DH;
    #pragma unroll
    for (int dt = 0; dt < 8; dt++) {
        int d = dt * 8 + 2 * lc;
        *(uint32_t*)(obase + (size_t)srow0 * CCH + d) =
            packh2(o[dt][0] * inv0, o[dt][1] * inv0);
        *(uint32_t*)(obase + (size_t)(srow0 + 8) * CCH + d) =
            packh2(o[dt][2] * inv1, o[dt][3] * inv1);
    }
}

// ============================================================
// Kernel 3: output projection (fp16 GEMM) + transpose store to [b][c][s]
// ============================================================
__global__ __launch_bounds__(256) void oproj2(const float* __restrict__ bo,
                                              float* __restrict__ out) {
    __shared__ GemmSmem S;
    const int tid = threadIdx.x, lane = tid & 31, warp = tid >> 5;
    const int wm = warp >> 2, wn = warp & 3, lr = lane >> 2, lc = lane & 3;

    const int m0 = blockIdx.y * 128;
    const int n0 = blockIdx.x * 128;
    const __half* Ag = g_attnout + (size_t)m0 * CCH;
    const __half* Bg = &g_wh[3][0] + (size_t)n0 * CCH;

    float acc[4][4][4];
    #pragma unroll
    for (int i = 0; i < 4; i++)
        #pragma unroll
        for (int j = 0; j < 4; j++)
            #pragma unroll
            for (int k = 0; k < 4; k++) acc[i][j][k] = 0.f;

    g_gemm(acc, &S, Ag, Bg, tid, lane, warp);

    #pragma unroll
    for (int mt = 0; mt < 4; mt++) {
        #pragma unroll
        for (int nt = 0; nt < 4; nt++) {
            int r = m0 + wm * 64 + mt * 16 + lr;
            int c = n0 + wn * 32 + nt * 8 + 2 * lc;
            int bb = r >> 12, ss = r & 4095;
            float bias0 = bo[c], bias1 = bo[c + 1];
            float* pc  = out + ((size_t)bb * CCH + c) * S_LEN;
            float* pc1 = pc + S_LEN;
            pc[ss]      = acc[mt][nt][0] + bias0;
            pc1[ss]     = acc[mt][nt][1] + bias1;
            pc[ss + 8]  = acc[mt][nt][2] + bias0;
            pc1[ss + 8] = acc[mt][nt][3] + bias1;
        }
    }
}

// ============================================================
extern "C" void kernel_launch(void* const* d_in, const int* in_sizes, int n_in,
                              void* d_out, int out_size)
{
    const float* x   = (const float*)d_in[0];
    const float* ctx = (const float*)d_in[1];
    const float* Wq  = (const float*)d_in[2];
    const float* bq  = (const float*)d_in[3];
    const float* Wk  = (const float*)d_in[4];
    const float* bk  = (const float*)d_in[5];
    const float* Wv  = (const float*)d_in[6];
    const float* bv  = (const float*)d_in[7];
    const float* Wo  = (const float*)d_in[8];
    const float* bo  = (const float*)d_in[9];
    float* out = (float*)d_out;

    cudaFuncSetAttribute(attn_kernel, cudaFuncAttributeMaxDynamicSharedMemorySize, SMEMA);

    prep_xh<<<dim3(128, 16, 4), 256>>>(x, ctx);
    prep_wh<<<dim3(256, 4), 256>>>(Wq, Wk, Wv, Wo);
    qkv2<<<dim3(4, 32, 6), 256>>>(bq, bk, bv);
    attn_kernel<<<dim3(32, 16), 256, SMEMA>>>();
    oproj2<<<dim3(4, 64), 256>>>(bo, out);
}

// round 17
// speedup vs baseline: 2.0273x; 1.0492x over previous
#include <cuda_runtime.h>
#include <cuda_fp16.h>
#include <cstdint>

#define S_LEN 4096
#define CCH   512
#define NH    8
#define DH    64
#define BATCH 2

// Scratch (all fp16 except noted)
__device__ __half g_q[(size_t)BATCH * NH * S_LEN * DH];    // [bh][s][d], pre-scaled 0.125*log2e
__device__ __half g_k[(size_t)BATCH * NH * S_LEN * DH];    // [bh][s][d]
__device__ __half g_v[(size_t)BATCH * NH * S_LEN * DH];    // [bh][d][s] TRANSPOSED
__device__ __half g_attnout[(size_t)BATCH * S_LEN * CCH];  // [b*4096+s][e]
__device__ __half g_xh[4][S_LEN][CCH];                     // {x b0, x b1, ctx b0, ctx b1} [s][c]
__device__ __half g_wh[4][CCH * CCH];                      // Wq,Wk,Wv,Wo [n][k]

__device__ __forceinline__ uint32_t packh2(float lo, float hi) {
    uint32_t r; asm("cvt.rn.f16x2.f32 %0, %1, %2;" : "=r"(r) : "f"(hi), "f"(lo)); return r;
}
__device__ __forceinline__ void mma16(float d[4], const uint32_t a[4], const uint32_t b[2]) {
    asm volatile(
        "mma.sync.aligned.m16n8k16.row.col.f32.f16.f16.f32 "
        "{%0,%1,%2,%3}, {%4,%5,%6,%7}, {%8,%9}, {%0,%1,%2,%3};\n"
        : "+f"(d[0]), "+f"(d[1]), "+f"(d[2]), "+f"(d[3])
        : "r"(a[0]), "r"(a[1]), "r"(a[2]), "r"(a[3]), "r"(b[0]), "r"(b[1]));
}
__device__ __forceinline__ void cp_async16(uint32_t s, const void* g) {
    asm volatile("cp.async.cg.shared.global [%0], [%1], 16;\n" :: "r"(s), "l"(g));
}
__device__ __forceinline__ void cp_commit() { asm volatile("cp.async.commit_group;\n"); }
template<int N> __device__ __forceinline__ void cp_wait() {
    asm volatile("cp.async.wait_group %0;\n" :: "n"(N));
}
__device__ __forceinline__ void ldsm4(uint32_t r[4], uint32_t addr) {
    asm volatile("ldmatrix.sync.aligned.m8n8.x4.shared.b16 {%0,%1,%2,%3}, [%4];"
        : "=r"(r[0]), "=r"(r[1]), "=r"(r[2]), "=r"(r[3]) : "r"(addr));
}

// ============================================================
// Prepass 1: transpose-convert x/ctx -> g_xh[z][s][c] fp16
// ============================================================
__global__ __launch_bounds__(256) void prep_xh(const float* __restrict__ x,
                                               const float* __restrict__ ctx) {
    __shared__ float t[32][33];
    const int z = blockIdx.z;
    const float* src = (z < 2 ? x : ctx) + (size_t)(z & 1) * CCH * S_LEN;
    const int c0 = blockIdx.y * 32, s0 = blockIdx.x * 32;
    const int tx = threadIdx.x & 31, ty = threadIdx.x >> 5;
    #pragma unroll
    for (int i = 0; i < 32; i += 8)
        t[ty + i][tx] = src[(size_t)(c0 + ty + i) * S_LEN + s0 + tx];
    __syncthreads();
    #pragma unroll
    for (int i = 0; i < 32; i += 8)
        g_xh[z][s0 + ty + i][c0 + tx] = __float2half_rn(t[tx][ty + i]);
}

// Prepass 2: convert W's -> fp16
__global__ __launch_bounds__(256) void prep_wh(const float* __restrict__ Wq,
                                               const float* __restrict__ Wk,
                                               const float* __restrict__ Wv,
                                               const float* __restrict__ Wo) {
    const int m = blockIdx.y;
    const float* src = (m == 0) ? Wq : (m == 1) ? Wk : (m == 2) ? Wv : Wo;
    int i = blockIdx.x * 256 + threadIdx.x;   // float4 index (65536/matrix)
    float4 v = ((const float4*)src)[i];
    uint2 o; o.x = packh2(v.x, v.y); o.y = packh2(v.z, v.w);
    ((uint2*)&g_wh[m][0])[i] = o;
}

// ============================================================
// fp16 GEMM core: 128m x 128n x (K=512, BK=32), double-buffered cp.async.
// ============================================================
#define GST (128 * 40)   // halves per stage per operand

__device__ __forceinline__ void g_fill(uint32_t sa, uint32_t sb,
                                       const __half* Ag, const __half* Bg,
                                       int kb, int tid) {
    #pragma unroll
    for (int i = 0; i < 2; i++) {
        int idx = tid + i * 256;
        int row = idx >> 2, c8 = idx & 3;
        cp_async16(sa + (uint32_t)(row * 40 + c8 * 8) * 2, Ag + (size_t)row * CCH + kb + c8 * 8);
        cp_async16(sb + (uint32_t)(row * 40 + c8 * 8) * 2, Bg + (size_t)row * CCH + kb + c8 * 8);
    }
}

struct GemmSmem { __half a[2][GST]; __half b[2][GST]; };

__device__ __forceinline__ void g_gemm(float acc[4][4][4], GemmSmem* S,
                                       const __half* Ag, const __half* Bg,
                                       int tid, int lane, int warp) {
    const int wm = warp >> 2, wn = warp & 3, lr = lane >> 2, lc = lane & 3;
    uint32_t smb = (uint32_t)__cvta_generic_to_shared(S);
    g_fill(smb + 0, smb + (uint32_t)(2 * GST) * 2, Ag, Bg, 0, tid);
    cp_commit();
    for (int s = 0; s < 16; s++) {
        const int p = s & 1;
        __syncthreads();
        if (s < 15) {
            const int q = p ^ 1;
            g_fill(smb + (uint32_t)(q * GST) * 2, smb + (uint32_t)((2 + q) * GST) * 2,
                   Ag, Bg, (s + 1) * 32, tid);
            cp_commit();
            cp_wait<1>();
        } else cp_wait<0>();
        __syncthreads();

        const __half* Ap = S->a[p];
        const __half* Bp = S->b[p];
        #pragma unroll
        for (int kk = 0; kk < 32; kk += 16) {
            uint32_t af[4][4];
            #pragma unroll
            for (int mt = 0; mt < 4; mt++) {
                int m = wm * 64 + mt * 16 + lr;
                af[mt][0] = *(const uint32_t*)&Ap[(size_t)m * 40 + kk + 2 * lc];
                af[mt][1] = *(const uint32_t*)&Ap[(size_t)(m + 8) * 40 + kk + 2 * lc];
                af[mt][2] = *(const uint32_t*)&Ap[(size_t)m * 40 + kk + 2 * lc + 8];
                af[mt][3] = *(const uint32_t*)&Ap[(size_t)(m + 8) * 40 + kk + 2 * lc + 8];
            }
            uint32_t bf[4][2];
            #pragma unroll
            for (int nt = 0; nt < 4; nt++) {
                int n = wn * 32 + nt * 8 + lr;
                bf[nt][0] = *(const uint32_t*)&Bp[(size_t)n * 40 + kk + 2 * lc];
                bf[nt][1] = *(const uint32_t*)&Bp[(size_t)n * 40 + kk + 2 * lc + 8];
            }
            #pragma unroll
            for (int mt = 0; mt < 4; mt++)
                #pragma unroll
                for (int nt = 0; nt < 4; nt++)
                    mma16(acc[mt][nt], af[mt], bf[nt]);
        }
    }
}

// ============================================================
// Kernel 1: QKV projections (fp16 GEMM; epilogue stores fp16, V transposed)
// Q scale folds 1/sqrt(d) AND log2(e) so softmax uses exp2 directly.
// ============================================================
__global__ __launch_bounds__(256) void qkv2(const float* __restrict__ bq,
                                            const float* __restrict__ bk,
                                            const float* __restrict__ bv) {
    __shared__ GemmSmem S;
    const int tid = threadIdx.x, lane = tid & 31, warp = tid >> 5;
    const int wm = warp >> 2, wn = warp & 3, lr = lane >> 2, lc = lane & 3;

    const int proj = blockIdx.z >> 1;
    const int b    = blockIdx.z & 1;
    const int s0   = blockIdx.y * 128;
    const int e0   = blockIdx.x * 128;
    const __half* Ag  = &g_xh[(proj == 0 ? 0 : 2) + b][s0][0];
    const __half* Bg  = &g_wh[proj][0] + (size_t)e0 * CCH;
    const float* bias = (proj == 0) ? bq : (proj == 1) ? bk : bv;
    __half* outbuf    = (proj == 0) ? g_q : (proj == 1) ? g_k : g_v;
    const float scale = (proj == 0) ? (0.125f * 1.44269504088896f) : 1.0f;
    const bool isV    = (proj == 2);

    float acc[4][4][4];
    #pragma unroll
    for (int i = 0; i < 4; i++)
        #pragma unroll
        for (int j = 0; j < 4; j++)
            #pragma unroll
            for (int k = 0; k < 4; k++) acc[i][j][k] = 0.f;

    g_gemm(acc, &S, Ag, Bg, tid, lane, warp);

    #pragma unroll
    for (int mt = 0; mt < 4; mt++) {
        #pragma unroll
        for (int nt = 0; nt < 4; nt++) {
            int r = s0 + wm * 64 + mt * 16 + lr;
            int c = e0 + wn * 32 + nt * 8 + 2 * lc;
            float b0 = bias[c], b1 = bias[c + 1];
            int h = c >> 6, d = c & 63;
            float v0 = (acc[mt][nt][0] + b0) * scale;
            float v1 = (acc[mt][nt][1] + b1) * scale;
            float v2 = (acc[mt][nt][2] + b0) * scale;
            float v3 = (acc[mt][nt][3] + b1) * scale;
            if (!isV) {
                __half* qb = outbuf + ((size_t)(b * NH + h) * S_LEN) * DH + d;
                *(uint32_t*)(qb + (size_t)r * DH)       = packh2(v0, v1);
                *(uint32_t*)(qb + (size_t)(r + 8) * DH) = packh2(v2, v3);
            } else {
                __half* vb = outbuf + ((size_t)(b * NH + h) * DH) * S_LEN;
                vb[(size_t)(d    ) * S_LEN + r]     = __float2half_rn(v0);
                vb[(size_t)(d + 1) * S_LEN + r]     = __float2half_rn(v1);
                vb[(size_t)(d    ) * S_LEN + r + 8] = __float2half_rn(v2);
                vb[(size_t)(d + 1) * S_LEN + r + 8] = __float2half_rn(v3);
            }
        }
    }
}

// ============================================================
// Kernel 2: flash attention, fp16 mma + ldmatrix; exp2 softmax;
// row-sums (l) accumulated via all-ones MMA column.
// smem (halves): Q[128][72] | K0,K1[64][72] | V0,V1[64][72]
// ============================================================
#define QH   (128 * 72)
#define KOFF(p) (QH + (p) * (64 * 72))
#define VOFF(p) (QH + 2 * 64 * 72 + (p) * (64 * 72))
#define SMEMA ((QH + 4 * 64 * 72) * 2)

__device__ __forceinline__ void fill_kv(uint32_t smb, const __half* Kg, const __half* Vg,
                                        int jt, int p, int tid)
{
    uint32_t kb = smb + KOFF(p) * 2;
    uint32_t vb = smb + VOFF(p) * 2;
    #pragma unroll
    for (int i = 0; i < 2; i++) {
        int idx = tid + i * 256;
        int j = idx >> 3, c8 = idx & 7;
        cp_async16(kb + (uint32_t)(j * 72 + c8 * 8) * 2, Kg + ((size_t)jt * 64 + j) * DH + c8 * 8);
        cp_async16(vb + (uint32_t)(j * 72 + c8 * 8) * 2, Vg + (size_t)j * S_LEN + jt * 64 + c8 * 8);
    }
}

__global__ __launch_bounds__(256) void attn_kernel()
{
    extern __shared__ __half smh[];
    const int qt = blockIdx.x, bh = blockIdx.y;
    const int tid = threadIdx.x, lane = tid & 31, warp = tid >> 5;
    const int lr = lane >> 2, lc = lane & 3;
    const int rbase = warp * 16;

    const __half* Qg = g_q + (size_t)bh * S_LEN * DH + (size_t)qt * 128 * DH;
    const __half* Kg = g_k + (size_t)bh * S_LEN * DH;
    const __half* Vg = g_v + (size_t)bh * S_LEN * DH;   // [d][s]

    uint32_t smb = (uint32_t)__cvta_generic_to_shared(smh);

    const int g8 = lane >> 3, r8 = lane & 7;
    const uint32_t tile_off = (uint32_t)((((g8 >> 1) << 3) + r8) * 72 + ((g8 & 1) << 3)) * 2;

    #pragma unroll
    for (int i = 0; i < 4; i++) {
        int idx = tid + i * 256;
        int j = idx >> 3, c8 = idx & 7;
        cp_async16(smb + (uint32_t)(j * 72 + c8 * 8) * 2, Qg + (size_t)j * DH + c8 * 8);
    }
    cp_commit();
    fill_kv(smb, Kg, Vg, 0, 0, tid);
    cp_commit();
    cp_wait<1>();
    __syncthreads();

    uint32_t qf[4][4];
    #pragma unroll
    for (int kt = 0; kt < 4; kt++) {
        int r = rbase + lr;
        qf[kt][0] = *(const uint32_t*)&smh[(size_t)r * 72 + kt * 16 + 2 * lc];
        qf[kt][1] = *(const uint32_t*)&smh[(size_t)(r + 8) * 72 + kt * 16 + 2 * lc];
        qf[kt][2] = *(const uint32_t*)&smh[(size_t)r * 72 + kt * 16 + 2 * lc + 8];
        qf[kt][3] = *(const uint32_t*)&smh[(size_t)(r + 8) * 72 + kt * 16 + 2 * lc + 8];
    }

    float o[8][4];
    #pragma unroll
    for (int i = 0; i < 8; i++)
        #pragma unroll
        for (int j = 0; j < 4; j++) o[i][j] = 0.f;
    float oex[4] = {0.f, 0.f, 0.f, 0.f};            // ones-column: row sums (l)
    float m0 = -1e30f, m1 = -1e30f;
    const uint32_t ONE2 = 0x3C003C00u;              // half2(1.0, 1.0)
    const uint32_t ones_bb[2] = {ONE2, ONE2};

    for (int jt = 0; jt < 64; jt++) {
        const int p = jt & 1;
        __syncthreads();
        if (jt < 63) { fill_kv(smb, Kg, Vg, jt + 1, p ^ 1, tid); cp_commit(); cp_wait<1>(); }
        else         { cp_wait<0>(); }
        __syncthreads();

        const uint32_t Kb = smb + KOFF(p) * 2 + tile_off;
        const uint32_t Vb = smb + VOFF(p) * 2 + tile_off;

        // S = Q K^T (logits already in log2 domain via Q scale)
        float s[8][4];
        #pragma unroll
        for (int i = 0; i < 8; i++)
            #pragma unroll
            for (int j2 = 0; j2 < 4; j2++) s[i][j2] = 0.f;

        #pragma unroll
        for (int kt = 0; kt < 4; kt++) {
            #pragma unroll
            for (int np = 0; np < 4; np++) {
                uint32_t bb[4];
                ldsm4(bb, Kb + (uint32_t)((np * 16 * 72 + kt * 16) * 2));
                mma16(s[2 * np],     qf[kt], bb);
                mma16(s[2 * np + 1], qf[kt], bb + 2);
            }
        }

        // Online softmax in log2 domain
        float mx0 = s[0][0], mx1 = s[0][2];
        #pragma unroll
        for (int nt = 0; nt < 8; nt++) {
            mx0 = fmaxf(mx0, fmaxf(s[nt][0], s[nt][1]));
            mx1 = fmaxf(mx1, fmaxf(s[nt][2], s[nt][3]));
        }
        mx0 = fmaxf(mx0, __shfl_xor_sync(0xffffffffu, mx0, 1));
        mx0 = fmaxf(mx0, __shfl_xor_sync(0xffffffffu, mx0, 2));
        mx1 = fmaxf(mx1, __shfl_xor_sync(0xffffffffu, mx1, 1));
        mx1 = fmaxf(mx1, __shfl_xor_sync(0xffffffffu, mx1, 2));
        float mn0 = fmaxf(m0, mx0), mn1 = fmaxf(m1, mx1);
        float f0 = exp2f(m0 - mn0), f1 = exp2f(m1 - mn1);
        #pragma unroll
        for (int nt = 0; nt < 8; nt++) {
            s[nt][0] = exp2f(s[nt][0] - mn0);
            s[nt][1] = exp2f(s[nt][1] - mn0);
            s[nt][2] = exp2f(s[nt][2] - mn1);
            s[nt][3] = exp2f(s[nt][3] - mn1);
        }
        m0 = mn0; m1 = mn1;
        if ((f0 != 1.f) | (f1 != 1.f)) {
            #pragma unroll
            for (int dt = 0; dt < 8; dt++) {
                o[dt][0] *= f0; o[dt][1] *= f0; o[dt][2] *= f1; o[dt][3] *= f1;
            }
            oex[0] *= f0; oex[1] *= f0; oex[2] *= f1; oex[3] *= f1;
        }

        // O += P V; l += P 1 (ones-column mma)
        #pragma unroll
        for (int kt = 0; kt < 4; kt++) {
            uint32_t a[4];
            a[0] = packh2(s[2 * kt][0],     s[2 * kt][1]);
            a[1] = packh2(s[2 * kt][2],     s[2 * kt][3]);
            a[2] = packh2(s[2 * kt + 1][0], s[2 * kt + 1][1]);
            a[3] = packh2(s[2 * kt + 1][2], s[2 * kt + 1][3]);
            #pragma unroll
            for (int dp = 0; dp < 4; dp++) {
                uint32_t bb[4];
                ldsm4(bb, Vb + (uint32_t)((dp * 16 * 72 + kt * 16) * 2));
                mma16(o[2 * dp],     a, bb);
                mma16(o[2 * dp + 1], a, bb + 2);
            }
            mma16(oex, a, ones_bb);
        }
    }

    // oex[0] = l(row lr), oex[2] = l(row lr+8) — every thread has them
    float inv0 = 1.f / oex[0], inv1 = 1.f / oex[2];
    const int b = bh >> 3, h = bh & 7;
    const int srow0 = qt * 128 + rbase + lr;
    __half* obase = g_attnout + (size_t)b * S_LEN * CCH + (size_t)h * DH;
    #pragma unroll
    for (int dt = 0; dt < 8; dt++) {
        int d = dt * 8 + 2 * lc;
        *(uint32_t*)(obase + (size_t)srow0 * CCH + d) =
            packh2(o[dt][0] * inv0, o[dt][1] * inv0);
        *(uint32_t*)(obase + (size_t)(srow0 + 8) * CCH + d) =
            packh2(o[dt][2] * inv1, o[dt][3] * inv1);
    }
}

// ============================================================
// Kernel 3: output projection (fp16 GEMM) + transpose store to [b][c][s]
// ============================================================
__global__ __launch_bounds__(256) void oproj2(const float* __restrict__ bo,
                                              float* __restrict__ out) {
    __shared__ GemmSmem S;
    const int tid = threadIdx.x, lane = tid & 31, warp = tid >> 5;
    const int wm = warp >> 2, wn = warp & 3, lr = lane >> 2, lc = lane & 3;

    const int m0 = blockIdx.y * 128;
    const int n0 = blockIdx.x * 128;
    const __half* Ag = g_attnout + (size_t)m0 * CCH;
    const __half* Bg = &g_wh[3][0] + (size_t)n0 * CCH;

    float acc[4][4][4];
    #pragma unroll
    for (int i = 0; i < 4; i++)
        #pragma unroll
        for (int j = 0; j < 4; j++)
            #pragma unroll
            for (int k = 0; k < 4; k++) acc[i][j][k] = 0.f;

    g_gemm(acc, &S, Ag, Bg, tid, lane, warp);

    #pragma unroll
    for (int mt = 0; mt < 4; mt++) {
        #pragma unroll
        for (int nt = 0; nt < 4; nt++) {
            int r = m0 + wm * 64 + mt * 16 + lr;
            int c = n0 + wn * 32 + nt * 8 + 2 * lc;
            int bb = r >> 12, ss = r & 4095;
            float bias0 = bo[c], bias1 = bo[c + 1];
            float* pc  = out + ((size_t)bb * CCH + c) * S_LEN;
            float* pc1 = pc + S_LEN;
            pc[ss]      = acc[mt][nt][0] + bias0;
            pc1[ss]     = acc[mt][nt][1] + bias1;
            pc[ss + 8]  = acc[mt][nt][2] + bias0;
            pc1[ss + 8] = acc[mt][nt][3] + bias1;
        }
    }
}

// ============================================================
extern "C" void kernel_launch(void* const* d_in, const int* in_sizes, int n_in,
                              void* d_out, int out_size)
{
    const float* x   = (const float*)d_in[0];
    const float* ctx = (const float*)d_in[1];
    const float* Wq  = (const float*)d_in[2];
    const float* bq  = (const float*)d_in[3];
    const float* Wk  = (const float*)d_in[4];
    const float* bk  = (const float*)d_in[5];
    const float* Wv  = (const float*)d_in[6];
    const float* bv  = (const float*)d_in[7];
    const float* Wo  = (const float*)d_in[8];
    const float* bo  = (const float*)d_in[9];
    float* out = (float*)d_out;

    cudaFuncSetAttribute(attn_kernel, cudaFuncAttributeMaxDynamicSharedMemorySize, SMEMA);

    prep_xh<<<dim3(128, 16, 4), 256>>>(x, ctx);
    prep_wh<<<dim3(256, 4), 256>>>(Wq, Wk, Wv, Wo);
    qkv2<<<dim3(4, 32, 6), 256>>>(bq, bk, bv);
    attn_kernel<<<dim3(32, 16), 256, SMEMA>>>();
    oproj2<<<dim3(4, 64), 256>>>(bo, out);
}